// round 13
// baseline (speedup 1.0000x reference)
#include <cuda_runtime.h>
#include <cstdint>

// ---------------------------------------------------------------------------
// ENGNLayer on GB300: LN -> edge MLP via mma.sync tf32 + scatter -> node MLP
// N=40000, E=640000, D=128.  (tcgen05 unavailable: harness PTX target is
// compute_103 without the 'a' feature set; mma.sync tf32 is baseline sm_80+.)
// ---------------------------------------------------------------------------

#define N_NODES 40000
#define N_EDGES 640000
#define D 128
#define LN_EPS 1e-5f

// Device scratch (allocation-free rule)
__device__ float g_h[N_NODES * D];      // LayerNorm output
__device__ float g_msum[N_NODES * D];   // scatter sum
__device__ float g_cnt[N_NODES];        // scatter count
__device__ float g_w1t[128 * 384];      // msg_w1 transposed [n][k], tf32-rounded
__device__ float g_w2t[128 * 128];      // msg_w2 transposed [n][k], tf32-rounded

__device__ __forceinline__ float silu(float x) { return x / (1.0f + __expf(-x)); }

__device__ __forceinline__ uint32_t f2tf(float f) {   // unbiased fp32 -> tf32
    uint32_t r;
    asm("cvt.rna.tf32.f32 %0, %1;" : "=r"(r) : "f"(f));
    return r;
}

// m16n8k8 tf32 MMA, D += A*B (fp32 accumulate)
__device__ __forceinline__ void mma_tf32(
    float& c0, float& c1, float& c2, float& c3,
    uint32_t a0, uint32_t a1, uint32_t a2, uint32_t a3,
    uint32_t b0, uint32_t b1)
{
    asm volatile(
        "mma.sync.aligned.m16n8k8.row.col.f32.tf32.tf32.f32 "
        "{%0,%1,%2,%3}, {%4,%5,%6,%7}, {%8,%9}, {%0,%1,%2,%3};"
        : "+f"(c0), "+f"(c1), "+f"(c2), "+f"(c3)
        : "r"(a0), "r"(a1), "r"(a2), "r"(a3), "r"(b0), "r"(b1));
}

// ---------------------------------------------------------------------------
// Kernel 0: transpose + tf32-round msg weights.  W1[384][128] -> W1t[128][384].
// ---------------------------------------------------------------------------
__global__ __launch_bounds__(256) void prep_weights(
    const float* __restrict__ w1, const float* __restrict__ w2)
{
    int i = blockIdx.x * 256 + threadIdx.x;
    if (i < 384 * 128) {
        int k = i >> 7, n = i & 127;
        g_w1t[n * 384 + k] = __uint_as_float(f2tf(w1[i]));
    } else {
        int j = i - 384 * 128;
        int k = j >> 7, n = j & 127;
        g_w2t[n * 128 + k] = __uint_as_float(f2tf(w2[j]));
    }
}

// ---------------------------------------------------------------------------
// Kernel 1: LayerNorm + zero scatter buffers.
// ---------------------------------------------------------------------------
__global__ __launch_bounds__(256) void ln_kernel(
    const float* __restrict__ nf,
    const float* __restrict__ gamma,
    const float* __restrict__ beta)
{
    int node = blockIdx.x * 8 + (threadIdx.x >> 5);
    int lane = threadIdx.x & 31;
    if (node >= N_NODES) return;

    float4 v = ((const float4*)(nf + (size_t)node * D))[lane];
    float s  = v.x + v.y + v.z + v.w;
    float sq = v.x * v.x + v.y * v.y + v.z * v.z + v.w * v.w;
    #pragma unroll
    for (int off = 16; off; off >>= 1) {
        s  += __shfl_xor_sync(0xFFFFFFFFu, s, off);
        sq += __shfl_xor_sync(0xFFFFFFFFu, sq, off);
    }
    float mu = s * (1.0f / D);
    float var = sq * (1.0f / D) - mu * mu;
    float rstd = rsqrtf(var + LN_EPS);

    float4 g = ((const float4*)gamma)[lane];
    float4 b = ((const float4*)beta)[lane];
    float4 h;
    h.x = (v.x - mu) * rstd * g.x + b.x;
    h.y = (v.y - mu) * rstd * g.y + b.y;
    h.z = (v.z - mu) * rstd * g.z + b.z;
    h.w = (v.w - mu) * rstd * g.w + b.w;
    ((float4*)(g_h + (size_t)node * D))[lane] = h;
    ((float4*)(g_msum + (size_t)node * D))[lane] = make_float4(0.f, 0.f, 0.f, 0.f);
    if (lane == 0) g_cnt[node] = 0.0f;
}

// ---------------------------------------------------------------------------
// Kernel 2: edge MLP on mma.sync tf32 + scatter.
// 128 edges/block, 256 threads (8 warps). Warp w -> rows [16w,16w+16), N=128.
// SMEM rows padded to 36 floats: frag-load bank = (4*row + k) % 32, conflict-free.
// Ms: 4 k-tiles of m1 (GEMM2 A); tile 0 doubles as GEMM1's A buffer.
// ---------------------------------------------------------------------------
#define PADK 36
#define TILE_B (128 * PADK * 4)          // 18432 bytes per [128][36] tile
#define BB_OFF (4 * TILE_B)              // 73728
#define MISC   (BB_OFF + TILE_B)         // 92160
#define EDGE_SMEM (MISC + 2048)          // 94208

__global__ __launch_bounds__(256, 2) void edge_kernel(
    const float* __restrict__ ef,
    const float* __restrict__ b1,
    const float* __restrict__ b2,
    const int*  __restrict__ src,
    const int*  __restrict__ dst)
{
    extern __shared__ char smem[];
    uint32_t* Ms = (uint32_t*)smem;                 // [4][128][PADK]
    uint32_t* As = Ms;                              // alias tile 0 (GEMM1 A)
    uint32_t* Bs = (uint32_t*)(smem + BB_OFF);      // [128][PADK]
    int*   s_src = (int*)(smem + MISC);
    int*   s_dst = (int*)(smem + MISC + 512);
    float* s_b1  = (float*)(smem + MISC + 1024);
    float* s_b2  = (float*)(smem + MISC + 1536);

    const int tid  = threadIdx.x;
    const int wid  = tid >> 5;
    const int lane = tid & 31;
    const int e0   = blockIdx.x * 128;

    if (tid < 128) { s_src[tid] = src[e0 + tid];             s_b1[tid] = b1[tid]; }
    else           { s_dst[tid - 128] = dst[e0 + tid - 128]; s_b2[tid - 128] = b2[tid - 128]; }

    const int lrow  = tid >> 1;          // loader: row 0..127
    const int lhalf = tid & 1;           // which 16-float half of 32-col tile
    const int qr = lane >> 2;            // fragment quad-row 0..7
    const int qc = lane & 3;             // fragment quad-col 0..3
    const int r0 = wid * 16;             // warp's output row base

    float acc[16][4];
    #pragma unroll
    for (int nt = 0; nt < 16; ++nt)
        #pragma unroll
        for (int j = 0; j < 4; ++j) acc[nt][j] = 0.0f;

    // ---------------- GEMM1: [128 x 384] @ W1t -> m1, 12 k-tiles of 32 ------
    for (int kt = 0; kt < 12; ++kt) {
        __syncthreads();   // prior iteration's fragment reads complete

        // A tile: gather row, round to tf32, store padded
        const float* ab;
        if (kt < 4)      ab = g_h + (size_t)s_src[lrow] * D + kt * 32;
        else if (kt < 8) ab = g_h + (size_t)s_dst[lrow] * D + (kt - 4) * 32;
        else             ab = ef  + (size_t)(e0 + lrow) * D + (kt - 8) * 32;
        ab += lhalf * 16;
        uint32_t* ap = As + lrow * PADK + lhalf * 16;
        #pragma unroll
        for (int j = 0; j < 4; ++j) {
            float4 v = *(const float4*)(ab + j * 4);
            uint4 t;
            t.x = f2tf(v.x); t.y = f2tf(v.y); t.z = f2tf(v.z); t.w = f2tf(v.w);
            *(uint4*)(ap + j * 4) = t;
        }
        // B tile: pre-rounded W1t[n][k]
        const float* wb = g_w1t + lrow * 384 + kt * 32 + lhalf * 16;
        uint32_t* bp = Bs + lrow * PADK + lhalf * 16;
        #pragma unroll
        for (int j = 0; j < 4; ++j)
            *(uint4*)(bp + j * 4) = *(const uint4*)(wb + j * 4);
        __syncthreads();

        // A fragments for 4 k-steps
        uint32_t a[4][4];
        #pragma unroll
        for (int ks = 0; ks < 4; ++ks) {
            int k0 = ks * 8;
            a[ks][0] = As[(r0 + qr)     * PADK + k0 + qc];
            a[ks][1] = As[(r0 + qr + 8) * PADK + k0 + qc];
            a[ks][2] = As[(r0 + qr)     * PADK + k0 + qc + 4];
            a[ks][3] = As[(r0 + qr + 8) * PADK + k0 + qc + 4];
        }
        #pragma unroll
        for (int nt = 0; nt < 16; ++nt) {
            const uint32_t* brow = Bs + (nt * 8 + qr) * PADK;
            #pragma unroll
            for (int ks = 0; ks < 4; ++ks) {
                uint32_t b0 = brow[ks * 8 + qc];
                uint32_t b1r = brow[ks * 8 + qc + 4];
                mma_tf32(acc[nt][0], acc[nt][1], acc[nt][2], acc[nt][3],
                         a[ks][0], a[ks][1], a[ks][2], a[ks][3], b0, b1r);
            }
        }
    }

    // ---- epilogue1: bias + silu -> tf32 -> Ms k-tiles (GEMM2 A operand) ----
    __syncthreads();   // all frag reads of As/Bs done before overwriting Ms
    #pragma unroll
    for (int nt = 0; nt < 16; ++nt) {
        #pragma unroll
        for (int j = 0; j < 4; ++j) {
            int row = r0 + qr + ((j >> 1) << 3);
            int col = nt * 8 + 2 * qc + (j & 1);
            float v = silu(acc[nt][j] + s_b1[col]);
            Ms[((col >> 5) * 128 + row) * PADK + (col & 31)] = f2tf(v);
            acc[nt][j] = 0.0f;
        }
    }

    // ---------------- GEMM2: m1 [128 x 128] @ W2t, 4 k-tiles ----------------
    for (int kt = 0; kt < 4; ++kt) {
        __syncthreads();   // Ms writes visible / prior Bs reads done
        const float* wb = g_w2t + lrow * 128 + kt * 32 + lhalf * 16;
        uint32_t* bp = Bs + lrow * PADK + lhalf * 16;
        #pragma unroll
        for (int j = 0; j < 4; ++j)
            *(uint4*)(bp + j * 4) = *(const uint4*)(wb + j * 4);
        __syncthreads();

        const uint32_t* Am = Ms + kt * 128 * PADK;
        uint32_t a[4][4];
        #pragma unroll
        for (int ks = 0; ks < 4; ++ks) {
            int k0 = ks * 8;
            a[ks][0] = Am[(r0 + qr)     * PADK + k0 + qc];
            a[ks][1] = Am[(r0 + qr + 8) * PADK + k0 + qc];
            a[ks][2] = Am[(r0 + qr)     * PADK + k0 + qc + 4];
            a[ks][3] = Am[(r0 + qr + 8) * PADK + k0 + qc + 4];
        }
        #pragma unroll
        for (int nt = 0; nt < 16; ++nt) {
            const uint32_t* brow = Bs + (nt * 8 + qr) * PADK;
            #pragma unroll
            for (int ks = 0; ks < 4; ++ks) {
                uint32_t b0 = brow[ks * 8 + qc];
                uint32_t b1r = brow[ks * 8 + qc + 4];
                mma_tf32(acc[nt][0], acc[nt][1], acc[nt][2], acc[nt][3],
                         a[ks][0], a[ks][1], a[ks][2], a[ks][3], b0, b1r);
            }
        }
    }

    // ---- final epilogue: bias + silu + red.add.v2 scatter into g_msum ------
    {
        const int rA = r0 + qr, rB = rA + 8;
        const int sA = s_src[rA], sB = s_src[rB];
        float* baseA = g_msum + (size_t)sA * D;
        float* baseB = g_msum + (size_t)sB * D;
        #pragma unroll
        for (int nt = 0; nt < 16; ++nt) {
            int c0 = nt * 8 + 2 * qc;
            float v0 = silu(acc[nt][0] + s_b2[c0]);
            float v1 = silu(acc[nt][1] + s_b2[c0 + 1]);
            float v2 = silu(acc[nt][2] + s_b2[c0]);
            float v3 = silu(acc[nt][3] + s_b2[c0 + 1]);
            asm volatile("red.global.add.v2.f32 [%0], {%1,%2};"
                         :: "l"(baseA + c0), "f"(v0), "f"(v1) : "memory");
            asm volatile("red.global.add.v2.f32 [%0], {%1,%2};"
                         :: "l"(baseB + c0), "f"(v2), "f"(v3) : "memory");
        }
        if (qc == 0) {
            atomicAdd(&g_cnt[sA], 1.0f);
            atomicAdd(&g_cnt[sB], 1.0f);
        }
    }
}

// ---------------------------------------------------------------------------
// Kernel 3: node aggregation MLP + residual (SIMT fp32, ~4 GFLOP).
// ---------------------------------------------------------------------------
#define NODE_SMEM (8192 + 16384 + 32768 + 256 + 512 + 512)

__global__ __launch_bounds__(256, 3) void node_kernel(
    const float* __restrict__ nf,
    const float* __restrict__ w1,  // [256,128]
    const float* __restrict__ b1,
    const float* __restrict__ w2,  // [128,128]
    const float* __restrict__ b2,
    float* __restrict__ out)
{
    extern __shared__ char smem_raw[];
    float* As    = (float*)smem_raw;
    float* Bs    = (float*)(smem_raw + 8192);
    float* Ms    = (float*)(smem_raw + 8192 + 16384);
    float* s_inv = (float*)(smem_raw + 8192 + 16384 + 32768);
    float* s_b1  = s_inv + 64;
    float* s_b2  = s_b1 + 128;

    const int tid = threadIdx.x;
    const int n0  = blockIdx.x * 64;

    if (tid < 64) {
        float c = g_cnt[n0 + tid];
        s_inv[tid] = 1.0f / fmaxf(c, 1.0f);
    }
    if (tid < 128) s_b1[tid] = b1[tid];
    else if (tid < 256) s_b2[tid - 128] = b2[tid - 128];
    __syncthreads();

    const int tx = tid & 31;
    const int ty = tid >> 5;
    const int row0 = ty * 8;
    const int col0 = tx * 4;
    const int arow = tid >> 2;
    const int acol = (tid & 3) * 8;

    float acc[8][4];
    #pragma unroll
    for (int i = 0; i < 8; i++)
        #pragma unroll
        for (int j = 0; j < 4; j++) acc[i][j] = 0.0f;

    for (int kt = 0; kt < 8; ++kt) {
        int seg = kt >> 2;
        int kin = (kt & 3) * 32;
        const float* abase = (seg == 0 ? g_h : g_msum) + (size_t)(n0 + arow) * D;
        float4 va = *(const float4*)(abase + kin + acol);
        float4 vb = *(const float4*)(abase + kin + acol + 4);
        if (seg == 1) {
            float inv = s_inv[arow];
            va.x *= inv; va.y *= inv; va.z *= inv; va.w *= inv;
            vb.x *= inv; vb.y *= inv; vb.z *= inv; vb.w *= inv;
        }
        *(float4*)(As + arow * 32 + acol)     = va;
        *(float4*)(As + arow * 32 + acol + 4) = vb;

        const float* wbase = w1 + kt * 32 * 128;
        #pragma unroll
        for (int i = 0; i < 4; i++) {
            int idx = (tid + i * 256) * 4;
            *(float4*)(Bs + idx) = *(const float4*)(wbase + idx);
        }
        __syncthreads();

        #pragma unroll
        for (int k = 0; k < 32; k++) {
            float4 bvec = *(const float4*)(Bs + k * 128 + col0);
            float a[8];
            #pragma unroll
            for (int i = 0; i < 8; i++) a[i] = As[(row0 + i) * 32 + k];
            #pragma unroll
            for (int i = 0; i < 8; i++) {
                acc[i][0] += a[i] * bvec.x; acc[i][1] += a[i] * bvec.y;
                acc[i][2] += a[i] * bvec.z; acc[i][3] += a[i] * bvec.w;
            }
        }
        __syncthreads();
    }

    {
        float bx = s_b1[col0], by = s_b1[col0 + 1], bz = s_b1[col0 + 2], bw = s_b1[col0 + 3];
        #pragma unroll
        for (int i = 0; i < 8; i++) {
            float4 v;
            v.x = silu(acc[i][0] + bx); v.y = silu(acc[i][1] + by);
            v.z = silu(acc[i][2] + bz); v.w = silu(acc[i][3] + bw);
            *(float4*)(Ms + (row0 + i) * 128 + col0) = v;
            acc[i][0] = 0.f; acc[i][1] = 0.f; acc[i][2] = 0.f; acc[i][3] = 0.f;
        }
    }
    __syncthreads();

    for (int kt = 0; kt < 4; ++kt) {
        const float* wbase = w2 + kt * 32 * 128;
        #pragma unroll
        for (int i = 0; i < 4; i++) {
            int idx = (tid + i * 256) * 4;
            *(float4*)(Bs + idx) = *(const float4*)(wbase + idx);
        }
        __syncthreads();
        #pragma unroll
        for (int k = 0; k < 32; k++) {
            int kk = kt * 32 + k;
            float4 bvec = *(const float4*)(Bs + k * 128 + col0);
            float a[8];
            #pragma unroll
            for (int i = 0; i < 8; i++) a[i] = Ms[(row0 + i) * 128 + kk];
            #pragma unroll
            for (int i = 0; i < 8; i++) {
                acc[i][0] += a[i] * bvec.x; acc[i][1] += a[i] * bvec.y;
                acc[i][2] += a[i] * bvec.z; acc[i][3] += a[i] * bvec.w;
            }
        }
        __syncthreads();
    }

    {
        float bx = s_b2[col0], by = s_b2[col0 + 1], bz = s_b2[col0 + 2], bw = s_b2[col0 + 3];
        #pragma unroll
        for (int i = 0; i < 8; i++) {
            int node = n0 + row0 + i;
            float4 res = *(const float4*)(nf + (size_t)node * D + col0);
            float4 v;
            v.x = res.x + silu(acc[i][0] + bx);
            v.y = res.y + silu(acc[i][1] + by);
            v.z = res.z + silu(acc[i][2] + bz);
            v.w = res.w + silu(acc[i][3] + bw);
            *(float4*)(out + (size_t)node * D + col0) = v;
        }
    }
}

// ---------------------------------------------------------------------------
extern "C" void kernel_launch(void* const* d_in, const int* in_sizes, int n_in,
                              void* d_out, int out_size)
{
    const float* nf    = (const float*)d_in[0];
    const float* ef    = (const float*)d_in[1];
    const float* gamma = (const float*)d_in[2];
    const float* beta  = (const float*)d_in[3];
    const float* mw1   = (const float*)d_in[4];
    const float* mb1   = (const float*)d_in[5];
    const float* mw2   = (const float*)d_in[6];
    const float* mb2   = (const float*)d_in[7];
    const float* aw1   = (const float*)d_in[8];
    const float* ab1   = (const float*)d_in[9];
    const float* aw2   = (const float*)d_in[10];
    const float* ab2   = (const float*)d_in[11];
    const int*   eidx  = (const int*)d_in[12];
    float*       out   = (float*)d_out;

    const int* src = eidx;
    const int* dst = eidx + N_EDGES;

    cudaFuncSetAttribute(edge_kernel, cudaFuncAttributeMaxDynamicSharedMemorySize, EDGE_SMEM);
    cudaFuncSetAttribute(node_kernel, cudaFuncAttributeMaxDynamicSharedMemorySize, NODE_SMEM);

    prep_weights<<<(384 * 128 + 128 * 128) / 256, 256>>>(mw1, mw2);
    ln_kernel<<<N_NODES / 8, 256>>>(nf, gamma, beta);
    edge_kernel<<<N_EDGES / 128, 256, EDGE_SMEM>>>(ef, mb1, mb2, src, dst);
    node_kernel<<<N_NODES / 64, 256, NODE_SMEM>>>(nf, aw1, ab1, aw2, ab2, out);
}

// round 14
// speedup vs baseline: 1.4524x; 1.4524x over previous
#include <cuda_runtime.h>
#include <cstdint>

// ---------------------------------------------------------------------------
// ENGNLayer on GB300: LN -> edge MLP via mma.sync bf16 + scatter -> node MLP
// via mma.sync bf16 + residual.  N=40000, E=640000, D=128.
// (tcgen05 unavailable: harness targets compute_103 baseline; mma.sync is
//  sm_80+ baseline. bf16 m16n8k16 halves MMA instruction count vs tf32 k8.)
// ---------------------------------------------------------------------------

#define N_NODES 40000
#define N_EDGES 640000
#define D 128
#define LN_EPS 1e-5f

// Device scratch (allocation-free rule)
__device__ float    g_h[N_NODES * D];      // LayerNorm output
__device__ float    g_msum[N_NODES * D];   // scatter sum
__device__ float    g_cnt[N_NODES];        // scatter count
__device__ uint32_t g_w1t[128 * 192];      // msg_w1^T  bf16x2  [n][k/2]
__device__ uint32_t g_w2t[128 * 64];       // msg_w2^T  bf16x2
__device__ uint32_t g_aw1t[128 * 128];     // agg_w1^T  bf16x2
__device__ uint32_t g_aw2t[128 * 64];      // agg_w2^T  bf16x2

__device__ __forceinline__ float silu(float x) { return x / (1.0f + __expf(-x)); }

// pack two f32 -> bf16x2 (lo = first arg, hi = second), round-nearest-even
__device__ __forceinline__ uint32_t packbf(float lo, float hi) {
    uint32_t r;
    asm("cvt.rn.bf16x2.f32 %0, %1, %2;" : "=r"(r) : "f"(hi), "f"(lo));
    return r;
}

// m16n8k16 bf16 MMA, D += A*B (fp32 accumulate)
__device__ __forceinline__ void mma_bf16(
    float& c0, float& c1, float& c2, float& c3,
    uint32_t a0, uint32_t a1, uint32_t a2, uint32_t a3,
    uint32_t b0, uint32_t b1)
{
    asm volatile(
        "mma.sync.aligned.m16n8k16.row.col.f32.bf16.bf16.f32 "
        "{%0,%1,%2,%3}, {%4,%5,%6,%7}, {%8,%9}, {%0,%1,%2,%3};"
        : "+f"(c0), "+f"(c1), "+f"(c2), "+f"(c3)
        : "r"(a0), "r"(a1), "r"(a2), "r"(a3), "r"(b0), "r"(b1));
}

// ---------------------------------------------------------------------------
// Kernel 0: transpose + bf16-pack all four weight matrices.
// Output word (n, wk) = { w[2wk][n] (lo), w[2wk+1][n] (hi) }.
// ---------------------------------------------------------------------------
__global__ __launch_bounds__(256) void prep_weights(
    const float* __restrict__ w1,  const float* __restrict__ w2,
    const float* __restrict__ aw1, const float* __restrict__ aw2)
{
    int i = blockIdx.x * 256 + threadIdx.x;
    if (i < 24576) {                       // w1t: [128][192]
        int n = i / 192, wk = i % 192;
        g_w1t[i] = packbf(w1[(2 * wk) * 128 + n], w1[(2 * wk + 1) * 128 + n]);
    } else if (i < 32768) {                // w2t: [128][64]
        int j = i - 24576, n = j / 64, wk = j % 64;
        g_w2t[j] = packbf(w2[(2 * wk) * 128 + n], w2[(2 * wk + 1) * 128 + n]);
    } else if (i < 49152) {                // aw1t: [128][128]
        int j = i - 32768, n = j / 128, wk = j % 128;
        g_aw1t[j] = packbf(aw1[(2 * wk) * 128 + n], aw1[(2 * wk + 1) * 128 + n]);
    } else if (i < 57344) {                // aw2t: [128][64]
        int j = i - 49152, n = j / 64, wk = j % 64;
        g_aw2t[j] = packbf(aw2[(2 * wk) * 128 + n], aw2[(2 * wk + 1) * 128 + n]);
    }
}

// ---------------------------------------------------------------------------
// Kernel 1: LayerNorm + zero scatter buffers.
// ---------------------------------------------------------------------------
__global__ __launch_bounds__(256) void ln_kernel(
    const float* __restrict__ nf,
    const float* __restrict__ gamma,
    const float* __restrict__ beta)
{
    int node = blockIdx.x * 8 + (threadIdx.x >> 5);
    int lane = threadIdx.x & 31;
    if (node >= N_NODES) return;

    float4 v = ((const float4*)(nf + (size_t)node * D))[lane];
    float s  = v.x + v.y + v.z + v.w;
    float sq = v.x * v.x + v.y * v.y + v.z * v.z + v.w * v.w;
    #pragma unroll
    for (int off = 16; off; off >>= 1) {
        s  += __shfl_xor_sync(0xFFFFFFFFu, s, off);
        sq += __shfl_xor_sync(0xFFFFFFFFu, sq, off);
    }
    float mu = s * (1.0f / D);
    float var = sq * (1.0f / D) - mu * mu;
    float rstd = rsqrtf(var + LN_EPS);

    float4 g = ((const float4*)gamma)[lane];
    float4 b = ((const float4*)beta)[lane];
    float4 h;
    h.x = (v.x - mu) * rstd * g.x + b.x;
    h.y = (v.y - mu) * rstd * g.y + b.y;
    h.z = (v.z - mu) * rstd * g.z + b.z;
    h.w = (v.w - mu) * rstd * g.w + b.w;
    ((float4*)(g_h + (size_t)node * D))[lane] = h;
    ((float4*)(g_msum + (size_t)node * D))[lane] = make_float4(0.f, 0.f, 0.f, 0.f);
    if (lane == 0) g_cnt[node] = 0.0f;
}

// ---------------------------------------------------------------------------
// Shared tile geometry: rows of 32 bf16 = 16 words, padded to 20 words.
// Frag/epilogue word index = row*20 + (0..7): banks (20*qr+qc)%32 cover all 32.
// ---------------------------------------------------------------------------
#define PADW 20
#define TILE_B (128 * PADW * 4)          // 10240 bytes per [128][32-bf16] tile
#define BB_OFF (4 * TILE_B)              // 40960
#define MISC   (BB_OFF + TILE_B)         // 51200
#define EDGE_SMEM (MISC + 2048)          // 53248
#define NODE_SMEM (MISC + 2048)

// ---------------------------------------------------------------------------
// Kernel 2: edge MLP on mma.sync bf16 + scatter.
// 128 edges/block, 8 warps; warp w -> rows [16w,16w+16), N=128.
// ---------------------------------------------------------------------------
__global__ __launch_bounds__(256, 2) void edge_kernel(
    const float* __restrict__ ef,
    const float* __restrict__ b1,
    const float* __restrict__ b2,
    const int*  __restrict__ src,
    const int*  __restrict__ dst)
{
    extern __shared__ char smem[];
    uint32_t* Ms = (uint32_t*)smem;                 // [4][128][PADW]
    uint32_t* As = Ms;                              // alias tile 0 (GEMM1 A)
    uint32_t* Bs = (uint32_t*)(smem + BB_OFF);      // [128][PADW]
    int*   s_src = (int*)(smem + MISC);
    int*   s_dst = (int*)(smem + MISC + 512);
    float* s_b1  = (float*)(smem + MISC + 1024);
    float* s_b2  = (float*)(smem + MISC + 1536);

    const int tid  = threadIdx.x;
    const int wid  = tid >> 5;
    const int lane = tid & 31;
    const int e0   = blockIdx.x * 128;

    if (tid < 128) { s_src[tid] = src[e0 + tid];             s_b1[tid] = b1[tid]; }
    else           { s_dst[tid - 128] = dst[e0 + tid - 128]; s_b2[tid - 128] = b2[tid - 128]; }

    const int lrow  = tid >> 1;          // loader: row 0..127
    const int lhalf = tid & 1;           // 16-float half of the 32-elem row
    const int qr = lane >> 2;
    const int qc = lane & 3;
    const int r0 = wid * 16;

    float acc[16][4];
    #pragma unroll
    for (int nt = 0; nt < 16; ++nt)
        #pragma unroll
        for (int j = 0; j < 4; ++j) acc[nt][j] = 0.0f;

    // ---------------- GEMM1: [128 x 384] @ W1t -> m1, 12 k-tiles of 32 ------
    for (int kt = 0; kt < 12; ++kt) {
        __syncthreads();

        // A tile: gather 16 floats, pack to 8 bf16x2 words
        const float* ab;
        if (kt < 4)      ab = g_h + (size_t)s_src[lrow] * D + kt * 32;
        else if (kt < 8) ab = g_h + (size_t)s_dst[lrow] * D + (kt - 4) * 32;
        else             ab = ef  + (size_t)(e0 + lrow) * D + (kt - 8) * 32;
        ab += lhalf * 16;
        uint32_t w[8];
        #pragma unroll
        for (int j = 0; j < 4; ++j) {
            float4 v = *(const float4*)(ab + j * 4);
            w[2 * j]     = packbf(v.x, v.y);
            w[2 * j + 1] = packbf(v.z, v.w);
        }
        uint32_t* ap = As + lrow * PADW + lhalf * 8;
        *(uint4*)(ap)     = make_uint4(w[0], w[1], w[2], w[3]);
        *(uint4*)(ap + 4) = make_uint4(w[4], w[5], w[6], w[7]);

        // B tile: pre-packed weights
        const uint32_t* wb = g_w1t + lrow * 192 + kt * 16 + lhalf * 8;
        uint32_t* bp = Bs + lrow * PADW + lhalf * 8;
        *(uint4*)(bp)     = *(const uint4*)(wb);
        *(uint4*)(bp + 4) = *(const uint4*)(wb + 4);
        __syncthreads();

        uint32_t a[2][4];
        #pragma unroll
        for (int ks = 0; ks < 2; ++ks) {
            int k0 = ks * 8;
            a[ks][0] = As[(r0 + qr)     * PADW + k0 + qc];
            a[ks][1] = As[(r0 + qr + 8) * PADW + k0 + qc];
            a[ks][2] = As[(r0 + qr)     * PADW + k0 + qc + 4];
            a[ks][3] = As[(r0 + qr + 8) * PADW + k0 + qc + 4];
        }
        #pragma unroll
        for (int nt = 0; nt < 16; ++nt) {
            const uint32_t* brow = Bs + (nt * 8 + qr) * PADW;
            #pragma unroll
            for (int ks = 0; ks < 2; ++ks)
                mma_bf16(acc[nt][0], acc[nt][1], acc[nt][2], acc[nt][3],
                         a[ks][0], a[ks][1], a[ks][2], a[ks][3],
                         brow[ks * 8 + qc], brow[ks * 8 + qc + 4]);
        }
    }

    // ---- epilogue1: bias + silu -> bf16x2 -> Ms k-tiles (GEMM2 A) ----------
    __syncthreads();
    #pragma unroll
    for (int nt = 0; nt < 16; ++nt) {
        int c0 = nt * 8 + 2 * qc;
        int wbase = (nt >> 2) * 128 * PADW + (nt & 3) * 4 + qc;
        float v0 = silu(acc[nt][0] + s_b1[c0]);
        float v1 = silu(acc[nt][1] + s_b1[c0 + 1]);
        float v2 = silu(acc[nt][2] + s_b1[c0]);
        float v3 = silu(acc[nt][3] + s_b1[c0 + 1]);
        Ms[wbase + (r0 + qr)     * PADW] = packbf(v0, v1);
        Ms[wbase + (r0 + qr + 8) * PADW] = packbf(v2, v3);
        acc[nt][0] = 0.f; acc[nt][1] = 0.f; acc[nt][2] = 0.f; acc[nt][3] = 0.f;
    }

    // ---------------- GEMM2: m1 [128 x 128] @ W2t, 4 k-tiles ----------------
    for (int kt = 0; kt < 4; ++kt) {
        __syncthreads();
        const uint32_t* wb = g_w2t + lrow * 64 + kt * 16 + lhalf * 8;
        uint32_t* bp = Bs + lrow * PADW + lhalf * 8;
        *(uint4*)(bp)     = *(const uint4*)(wb);
        *(uint4*)(bp + 4) = *(const uint4*)(wb + 4);
        __syncthreads();

        const uint32_t* Am = Ms + kt * 128 * PADW;
        uint32_t a[2][4];
        #pragma unroll
        for (int ks = 0; ks < 2; ++ks) {
            int k0 = ks * 8;
            a[ks][0] = Am[(r0 + qr)     * PADW + k0 + qc];
            a[ks][1] = Am[(r0 + qr + 8) * PADW + k0 + qc];
            a[ks][2] = Am[(r0 + qr)     * PADW + k0 + qc + 4];
            a[ks][3] = Am[(r0 + qr + 8) * PADW + k0 + qc + 4];
        }
        #pragma unroll
        for (int nt = 0; nt < 16; ++nt) {
            const uint32_t* brow = Bs + (nt * 8 + qr) * PADW;
            #pragma unroll
            for (int ks = 0; ks < 2; ++ks)
                mma_bf16(acc[nt][0], acc[nt][1], acc[nt][2], acc[nt][3],
                         a[ks][0], a[ks][1], a[ks][2], a[ks][3],
                         brow[ks * 8 + qc], brow[ks * 8 + qc + 4]);
        }
    }

    // ---- final epilogue: bias + silu + red.add.v2 scatter into g_msum ------
    {
        const int rA = r0 + qr, rB = rA + 8;
        const int sA = s_src[rA], sB = s_src[rB];
        float* baseA = g_msum + (size_t)sA * D;
        float* baseB = g_msum + (size_t)sB * D;
        #pragma unroll
        for (int nt = 0; nt < 16; ++nt) {
            int c0 = nt * 8 + 2 * qc;
            float v0 = silu(acc[nt][0] + s_b2[c0]);
            float v1 = silu(acc[nt][1] + s_b2[c0 + 1]);
            float v2 = silu(acc[nt][2] + s_b2[c0]);
            float v3 = silu(acc[nt][3] + s_b2[c0 + 1]);
            asm volatile("red.global.add.v2.f32 [%0], {%1,%2};"
                         :: "l"(baseA + c0), "f"(v0), "f"(v1) : "memory");
            asm volatile("red.global.add.v2.f32 [%0], {%1,%2};"
                         :: "l"(baseB + c0), "f"(v2), "f"(v3) : "memory");
        }
        if (qc == 0) {
            atomicAdd(&g_cnt[sA], 1.0f);
            atomicAdd(&g_cnt[sB], 1.0f);
        }
    }
}

// ---------------------------------------------------------------------------
// Kernel 3: node aggregation MLP + residual on mma.sync bf16.
// 128 nodes/block, 313 blocks (tail clamped/guarded).
// ---------------------------------------------------------------------------
__global__ __launch_bounds__(256, 2) void node_kernel(
    const float* __restrict__ nf,
    const float* __restrict__ b1,
    const float* __restrict__ b2,
    float* __restrict__ out)
{
    extern __shared__ char smem[];
    uint32_t* Ms = (uint32_t*)smem;
    uint32_t* As = Ms;
    uint32_t* Bs = (uint32_t*)(smem + BB_OFF);
    float* s_inv = (float*)(smem + MISC);
    float* s_b1  = (float*)(smem + MISC + 512);
    float* s_b2  = (float*)(smem + MISC + 1024);

    const int tid  = threadIdx.x;
    const int wid  = tid >> 5;
    const int lane = tid & 31;
    const int n0   = blockIdx.x * 128;

    if (tid < 128) {
        int nd = min(n0 + tid, N_NODES - 1);
        s_inv[tid] = 1.0f / fmaxf(g_cnt[nd], 1.0f);
        s_b1[tid]  = b1[tid];
    } else {
        s_b2[tid - 128] = b2[tid - 128];
    }

    const int lrow  = tid >> 1;
    const int lhalf = tid & 1;
    const int qr = lane >> 2;
    const int qc = lane & 3;
    const int r0 = wid * 16;
    const int lnode = min(n0 + lrow, N_NODES - 1);

    float acc[16][4];
    #pragma unroll
    for (int nt = 0; nt < 16; ++nt)
        #pragma unroll
        for (int j = 0; j < 4; ++j) acc[nt][j] = 0.0f;

    // ---- GEMM1: concat(h, mean) [128 x 256] @ AW1t, 8 k-tiles --------------
    for (int kt = 0; kt < 8; ++kt) {
        __syncthreads();

        const float* ab = (kt < 4 ? g_h : g_msum)
                          + (size_t)lnode * D + (kt & 3) * 32 + lhalf * 16;
        float inv = (kt < 4) ? 1.0f : s_inv[lrow];
        uint32_t w[8];
        #pragma unroll
        for (int j = 0; j < 4; ++j) {
            float4 v = *(const float4*)(ab + j * 4);
            w[2 * j]     = packbf(v.x * inv, v.y * inv);
            w[2 * j + 1] = packbf(v.z * inv, v.w * inv);
        }
        uint32_t* ap = As + lrow * PADW + lhalf * 8;
        *(uint4*)(ap)     = make_uint4(w[0], w[1], w[2], w[3]);
        *(uint4*)(ap + 4) = make_uint4(w[4], w[5], w[6], w[7]);

        const uint32_t* wb = g_aw1t + lrow * 128 + kt * 16 + lhalf * 8;
        uint32_t* bp = Bs + lrow * PADW + lhalf * 8;
        *(uint4*)(bp)     = *(const uint4*)(wb);
        *(uint4*)(bp + 4) = *(const uint4*)(wb + 4);
        __syncthreads();

        uint32_t a[2][4];
        #pragma unroll
        for (int ks = 0; ks < 2; ++ks) {
            int k0 = ks * 8;
            a[ks][0] = As[(r0 + qr)     * PADW + k0 + qc];
            a[ks][1] = As[(r0 + qr + 8) * PADW + k0 + qc];
            a[ks][2] = As[(r0 + qr)     * PADW + k0 + qc + 4];
            a[ks][3] = As[(r0 + qr + 8) * PADW + k0 + qc + 4];
        }
        #pragma unroll
        for (int nt = 0; nt < 16; ++nt) {
            const uint32_t* brow = Bs + (nt * 8 + qr) * PADW;
            #pragma unroll
            for (int ks = 0; ks < 2; ++ks)
                mma_bf16(acc[nt][0], acc[nt][1], acc[nt][2], acc[nt][3],
                         a[ks][0], a[ks][1], a[ks][2], a[ks][3],
                         brow[ks * 8 + qc], brow[ks * 8 + qc + 4]);
        }
    }

    // ---- epilogue1 -> Ms ----------------------------------------------------
    __syncthreads();
    #pragma unroll
    for (int nt = 0; nt < 16; ++nt) {
        int c0 = nt * 8 + 2 * qc;
        int wbase = (nt >> 2) * 128 * PADW + (nt & 3) * 4 + qc;
        float v0 = silu(acc[nt][0] + s_b1[c0]);
        float v1 = silu(acc[nt][1] + s_b1[c0 + 1]);
        float v2 = silu(acc[nt][2] + s_b1[c0]);
        float v3 = silu(acc[nt][3] + s_b1[c0 + 1]);
        Ms[wbase + (r0 + qr)     * PADW] = packbf(v0, v1);
        Ms[wbase + (r0 + qr + 8) * PADW] = packbf(v2, v3);
        acc[nt][0] = 0.f; acc[nt][1] = 0.f; acc[nt][2] = 0.f; acc[nt][3] = 0.f;
    }

    // ---- GEMM2: [128 x 128] @ AW2t, 4 k-tiles -------------------------------
    for (int kt = 0; kt < 4; ++kt) {
        __syncthreads();
        const uint32_t* wb = g_aw2t + lrow * 64 + kt * 16 + lhalf * 8;
        uint32_t* bp = Bs + lrow * PADW + lhalf * 8;
        *(uint4*)(bp)     = *(const uint4*)(wb);
        *(uint4*)(bp + 4) = *(const uint4*)(wb + 4);
        __syncthreads();

        const uint32_t* Am = Ms + kt * 128 * PADW;
        uint32_t a[2][4];
        #pragma unroll
        for (int ks = 0; ks < 2; ++ks) {
            int k0 = ks * 8;
            a[ks][0] = Am[(r0 + qr)     * PADW + k0 + qc];
            a[ks][1] = Am[(r0 + qr + 8) * PADW + k0 + qc];
            a[ks][2] = Am[(r0 + qr)     * PADW + k0 + qc + 4];
            a[ks][3] = Am[(r0 + qr + 8) * PADW + k0 + qc + 4];
        }
        #pragma unroll
        for (int nt = 0; nt < 16; ++nt) {
            const uint32_t* brow = Bs + (nt * 8 + qr) * PADW;
            #pragma unroll
            for (int ks = 0; ks < 2; ++ks)
                mma_bf16(acc[nt][0], acc[nt][1], acc[nt][2], acc[nt][3],
                         a[ks][0], a[ks][1], a[ks][2], a[ks][3],
                         brow[ks * 8 + qc], brow[ks * 8 + qc + 4]);
        }
    }

    // ---- final: bias + silu + residual -> out (guard tail) ------------------
    {
        const int nA = n0 + r0 + qr, nB = nA + 8;
        #pragma unroll
        for (int nt = 0; nt < 16; ++nt) {
            int c0 = nt * 8 + 2 * qc;
            if (nA < N_NODES) {
                float2 r = *(const float2*)(nf + (size_t)nA * D + c0);
                float2 o;
                o.x = r.x + silu(acc[nt][0] + s_b2[c0]);
                o.y = r.y + silu(acc[nt][1] + s_b2[c0 + 1]);
                *(float2*)(out + (size_t)nA * D + c0) = o;
            }
            if (nB < N_NODES) {
                float2 r = *(const float2*)(nf + (size_t)nB * D + c0);
                float2 o;
                o.x = r.x + silu(acc[nt][2] + s_b2[c0]);
                o.y = r.y + silu(acc[nt][3] + s_b2[c0 + 1]);
                *(float2*)(out + (size_t)nB * D + c0) = o;
            }
        }
    }
}

// ---------------------------------------------------------------------------
extern "C" void kernel_launch(void* const* d_in, const int* in_sizes, int n_in,
                              void* d_out, int out_size)
{
    const float* nf    = (const float*)d_in[0];
    const float* ef    = (const float*)d_in[1];
    const float* gamma = (const float*)d_in[2];
    const float* beta  = (const float*)d_in[3];
    const float* mw1   = (const float*)d_in[4];
    const float* mb1   = (const float*)d_in[5];
    const float* mw2   = (const float*)d_in[6];
    const float* mb2   = (const float*)d_in[7];
    const float* aw1   = (const float*)d_in[8];
    const float* ab1   = (const float*)d_in[9];
    const float* aw2   = (const float*)d_in[10];
    const float* ab2   = (const float*)d_in[11];
    const int*   eidx  = (const int*)d_in[12];
    float*       out   = (float*)d_out;

    const int* src = eidx;
    const int* dst = eidx + N_EDGES;

    cudaFuncSetAttribute(edge_kernel, cudaFuncAttributeMaxDynamicSharedMemorySize, EDGE_SMEM);
    cudaFuncSetAttribute(node_kernel, cudaFuncAttributeMaxDynamicSharedMemorySize, NODE_SMEM);

    prep_weights<<<224, 256>>>(mw1, mw2, aw1, aw2);
    ln_kernel<<<N_NODES / 8, 256>>>(nf, gamma, beta);
    edge_kernel<<<N_EDGES / 128, 256, EDGE_SMEM>>>(ef, mb1, mb2, src, dst);
    node_kernel<<<(N_NODES + 127) / 128, 256, NODE_SMEM>>>(nf, ab1, ab2, out);
}

// round 15
// speedup vs baseline: 1.4829x; 1.0210x over previous
#include <cuda_runtime.h>
#include <cstdint>

// ---------------------------------------------------------------------------
// ENGNLayer on GB300: LN -> edge MLP (mma.sync f16 + ldmatrix) + scatter ->
// node MLP (same path) + residual.  N=40000, E=640000, D=128.
// fp16 operands (10 mantissa bits ~ tf32 precision), fp32 accumulate.
// ldmatrix fragment loads + single-sync ping-pong staging.
// ---------------------------------------------------------------------------

#define N_NODES 40000
#define N_EDGES 640000
#define D 128
#define LN_EPS 1e-5f

// Device scratch (allocation-free rule)
__device__ float    g_h[N_NODES * D];      // LayerNorm output
__device__ float    g_msum[N_NODES * D];   // scatter sum
__device__ float    g_cnt[N_NODES];        // scatter count
__device__ uint32_t g_w1t[128 * 192];      // msg_w1^T  f16x2  [n][k/2]
__device__ uint32_t g_w2t[128 * 64];       // msg_w2^T  f16x2
__device__ uint32_t g_aw1t[128 * 128];     // agg_w1^T  f16x2
__device__ uint32_t g_aw2t[128 * 64];      // agg_w2^T  f16x2

__device__ __forceinline__ float silu(float x) { return x / (1.0f + __expf(-x)); }

// pack two f32 -> f16x2 (lo = first arg, hi = second), round-nearest-even
__device__ __forceinline__ uint32_t packh(float lo, float hi) {
    uint32_t r;
    asm("cvt.rn.f16x2.f32 %0, %1, %2;" : "=r"(r) : "f"(hi), "f"(lo));
    return r;
}

__device__ __forceinline__ uint32_t smem_u32(const void* p) {
    uint32_t a;
    asm("{ .reg .u64 t; cvta.to.shared.u64 t, %1; cvt.u32.u64 %0, t; }" : "=r"(a) : "l"(p));
    return a;
}

// m16n8k16 f16 MMA, D += A*B (fp32 accumulate)
__device__ __forceinline__ void mma_f16(
    float& c0, float& c1, float& c2, float& c3,
    uint32_t a0, uint32_t a1, uint32_t a2, uint32_t a3,
    uint32_t b0, uint32_t b1)
{
    asm volatile(
        "mma.sync.aligned.m16n8k16.row.col.f32.f16.f16.f32 "
        "{%0,%1,%2,%3}, {%4,%5,%6,%7}, {%8,%9}, {%0,%1,%2,%3};"
        : "+f"(c0), "+f"(c1), "+f"(c2), "+f"(c3)
        : "r"(a0), "r"(a1), "r"(a2), "r"(a3), "r"(b0), "r"(b1));
}

__device__ __forceinline__ void ldsm_x4(
    uint32_t& r0, uint32_t& r1, uint32_t& r2, uint32_t& r3, uint32_t addr)
{
    asm volatile("ldmatrix.sync.aligned.m8n8.x4.shared.b16 {%0,%1,%2,%3}, [%4];"
                 : "=r"(r0), "=r"(r1), "=r"(r2), "=r"(r3) : "r"(addr));
}

// ---------------------------------------------------------------------------
// Kernel 0: transpose + f16-pack all four weight matrices.
// ---------------------------------------------------------------------------
__global__ __launch_bounds__(256) void prep_weights(
    const float* __restrict__ w1,  const float* __restrict__ w2,
    const float* __restrict__ aw1, const float* __restrict__ aw2)
{
    int i = blockIdx.x * 256 + threadIdx.x;
    if (i < 24576) {                       // w1t: [128][192]
        int n = i / 192, wk = i % 192;
        g_w1t[i] = packh(w1[(2 * wk) * 128 + n], w1[(2 * wk + 1) * 128 + n]);
    } else if (i < 32768) {                // w2t: [128][64]
        int j = i - 24576, n = j / 64, wk = j % 64;
        g_w2t[j] = packh(w2[(2 * wk) * 128 + n], w2[(2 * wk + 1) * 128 + n]);
    } else if (i < 49152) {                // aw1t: [128][128]
        int j = i - 32768, n = j / 128, wk = j % 128;
        g_aw1t[j] = packh(aw1[(2 * wk) * 128 + n], aw1[(2 * wk + 1) * 128 + n]);
    } else if (i < 57344) {                // aw2t: [128][64]
        int j = i - 49152, n = j / 64, wk = j % 64;
        g_aw2t[j] = packh(aw2[(2 * wk) * 128 + n], aw2[(2 * wk + 1) * 128 + n]);
    }
}

// ---------------------------------------------------------------------------
// Kernel 1: LayerNorm + zero scatter buffers.
// ---------------------------------------------------------------------------
__global__ __launch_bounds__(256) void ln_kernel(
    const float* __restrict__ nf,
    const float* __restrict__ gamma,
    const float* __restrict__ beta)
{
    int node = blockIdx.x * 8 + (threadIdx.x >> 5);
    int lane = threadIdx.x & 31;
    if (node >= N_NODES) return;

    float4 v = ((const float4*)(nf + (size_t)node * D))[lane];
    float s  = v.x + v.y + v.z + v.w;
    float sq = v.x * v.x + v.y * v.y + v.z * v.z + v.w * v.w;
    #pragma unroll
    for (int off = 16; off; off >>= 1) {
        s  += __shfl_xor_sync(0xFFFFFFFFu, s, off);
        sq += __shfl_xor_sync(0xFFFFFFFFu, sq, off);
    }
    float mu = s * (1.0f / D);
    float var = sq * (1.0f / D) - mu * mu;
    float rstd = rsqrtf(var + LN_EPS);

    float4 g = ((const float4*)gamma)[lane];
    float4 b = ((const float4*)beta)[lane];
    float4 h;
    h.x = (v.x - mu) * rstd * g.x + b.x;
    h.y = (v.y - mu) * rstd * g.y + b.y;
    h.z = (v.z - mu) * rstd * g.z + b.z;
    h.w = (v.w - mu) * rstd * g.w + b.w;
    ((float4*)(g_h + (size_t)node * D))[lane] = h;
    ((float4*)(g_msum + (size_t)node * D))[lane] = make_float4(0.f, 0.f, 0.f, 0.f);
    if (lane == 0) g_cnt[node] = 0.0f;
}

// ---------------------------------------------------------------------------
// Tile geometry: a tile = [128 rows][32 f16 = 16 words], rows padded to 20
// words (80B). ldmatrix octets hit all 32 banks ((20r)%32 distinct).
// 6 tiles: 0-3 = staging (GEMM1) then m1 k-slices; 4-5 = GEMM2 B ping-pong.
// ---------------------------------------------------------------------------
#define PADW 20
#define TILE_W (128 * PADW)              // words per tile (2560)
#define TILE_B (TILE_W * 4)              // 10240 bytes
#define MISC_OFF (6 * TILE_B)            // 61440
#define SMEM_SZ (MISC_OFF + 2048)        // 63488

// ---------------------------------------------------------------------------
// Kernel 2: edge MLP + scatter. 128 edges/block, 8 warps.
// ---------------------------------------------------------------------------
__global__ __launch_bounds__(256, 2) void edge_kernel(
    const float* __restrict__ ef,
    const float* __restrict__ b1,
    const float* __restrict__ b2,
    const int*  __restrict__ src,
    const int*  __restrict__ dst)
{
    extern __shared__ char smem[];
    uint32_t* W = (uint32_t*)smem;
    int*   s_src = (int*)(smem + MISC_OFF);
    int*   s_dst = (int*)(smem + MISC_OFF + 512);
    float* s_b1  = (float*)(smem + MISC_OFF + 1024);
    float* s_b2  = (float*)(smem + MISC_OFF + 1536);
    const uint32_t sb = smem_u32(smem);

    const int tid  = threadIdx.x;
    const int wid  = tid >> 5;
    const int lane = tid & 31;
    const int e0   = blockIdx.x * 128;

    if (tid < 128) { s_src[tid] = src[e0 + tid];             s_b1[tid] = b1[tid]; }
    else           { s_dst[tid - 128] = dst[e0 + tid - 128]; s_b2[tid - 128] = b2[tid - 128]; }
    __syncthreads();

    const int lrow  = tid >> 1;          // staging row 0..127
    const int lhalf = tid & 1;
    const int qr = lane >> 2;
    const int qc = lane & 3;
    const int r0 = wid * 16;

    // per-lane ldmatrix byte offsets (within a tile)
    const uint32_t laneA = sb +
        (((uint32_t)(r0 + (lane & 7) + ((lane >> 3) & 1) * 8) * PADW + (lane >> 4) * 4) << 2);
    const uint32_t laneB = sb +
        (((uint32_t)((lane & 7) + ((lane >> 4) & 1) * 8) * PADW + ((lane >> 3) & 1) * 4) << 2);

    float acc[16][4];
    #pragma unroll
    for (int nt = 0; nt < 16; ++nt)
        #pragma unroll
        for (int j = 0; j < 4; ++j) acc[nt][j] = 0.0f;

    // ---------------- GEMM1: [128 x 384] @ W1t, 12 k-tiles of 32 ------------
    for (int kt = 0; kt < 12; ++kt) {
        const int b = kt & 1;

        // stage A (gather + f16 pack)
        const float* ab;
        if (kt < 4)      ab = g_h + (size_t)s_src[lrow] * D + kt * 32;
        else if (kt < 8) ab = g_h + (size_t)s_dst[lrow] * D + (kt - 4) * 32;
        else             ab = ef  + (size_t)(e0 + lrow) * D + (kt - 8) * 32;
        ab += lhalf * 16;
        uint32_t w[8];
        #pragma unroll
        for (int j = 0; j < 4; ++j) {
            float4 v = *(const float4*)(ab + j * 4);
            w[2 * j]     = packh(v.x, v.y);
            w[2 * j + 1] = packh(v.z, v.w);
        }
        uint32_t* ap = W + b * TILE_W + lrow * PADW + lhalf * 8;
        *(uint4*)(ap)     = make_uint4(w[0], w[1], w[2], w[3]);
        *(uint4*)(ap + 4) = make_uint4(w[4], w[5], w[6], w[7]);

        // stage B (pre-packed weights)
        const uint32_t* wb = g_w1t + lrow * 192 + kt * 16 + lhalf * 8;
        uint32_t* bp = W + (2 + b) * TILE_W + lrow * PADW + lhalf * 8;
        *(uint4*)(bp)     = *(const uint4*)(wb);
        *(uint4*)(bp + 4) = *(const uint4*)(wb + 4);
        __syncthreads();

        const uint32_t aA = laneA + b * TILE_B;
        const uint32_t bA = laneB + (2 + b) * TILE_B;
        #pragma unroll
        for (int ks = 0; ks < 2; ++ks) {
            uint32_t a0, a1, a2, a3;
            ldsm_x4(a0, a1, a2, a3, aA + ks * 32);
            #pragma unroll
            for (int ntp = 0; ntp < 8; ++ntp) {
                uint32_t bb0, bb1, bb2, bb3;
                ldsm_x4(bb0, bb1, bb2, bb3, bA + ks * 32 + ntp * (16 * PADW * 4));
                mma_f16(acc[2 * ntp][0], acc[2 * ntp][1], acc[2 * ntp][2], acc[2 * ntp][3],
                        a0, a1, a2, a3, bb0, bb1);
                mma_f16(acc[2 * ntp + 1][0], acc[2 * ntp + 1][1],
                        acc[2 * ntp + 1][2], acc[2 * ntp + 1][3],
                        a0, a1, a2, a3, bb2, bb3);
            }
        }
    }
    __syncthreads();   // all GEMM1 reads of tiles 0-3 done before Ms writes

    // ---- epilogue1: bias + silu -> f16x2 -> Ms k-slices (tiles 0-3) --------
    #pragma unroll
    for (int nt = 0; nt < 16; ++nt) {
        int c0 = nt * 8 + 2 * qc;
        int wbase = (nt >> 2) * TILE_W + (nt & 3) * 4 + qc;
        float v0 = silu(acc[nt][0] + s_b1[c0]);
        float v1 = silu(acc[nt][1] + s_b1[c0 + 1]);
        float v2 = silu(acc[nt][2] + s_b1[c0]);
        float v3 = silu(acc[nt][3] + s_b1[c0 + 1]);
        W[wbase + (r0 + qr)     * PADW] = packh(v0, v1);
        W[wbase + (r0 + qr + 8) * PADW] = packh(v2, v3);
        acc[nt][0] = 0.f; acc[nt][1] = 0.f; acc[nt][2] = 0.f; acc[nt][3] = 0.f;
    }

    // ---------------- GEMM2: m1 [128 x 128] @ W2t, 4 k-tiles ----------------
    for (int kt = 0; kt < 4; ++kt) {
        const int b = kt & 1;
        const uint32_t* wb = g_w2t + lrow * 64 + kt * 16 + lhalf * 8;
        uint32_t* bp = W + (4 + b) * TILE_W + lrow * PADW + lhalf * 8;
        *(uint4*)(bp)     = *(const uint4*)(wb);
        *(uint4*)(bp + 4) = *(const uint4*)(wb + 4);
        __syncthreads();   // also orders epilogue1 Ms writes on kt==0

        const uint32_t aA = laneA + kt * TILE_B;
        const uint32_t bA = laneB + (4 + b) * TILE_B;
        #pragma unroll
        for (int ks = 0; ks < 2; ++ks) {
            uint32_t a0, a1, a2, a3;
            ldsm_x4(a0, a1, a2, a3, aA + ks * 32);
            #pragma unroll
            for (int ntp = 0; ntp < 8; ++ntp) {
                uint32_t bb0, bb1, bb2, bb3;
                ldsm_x4(bb0, bb1, bb2, bb3, bA + ks * 32 + ntp * (16 * PADW * 4));
                mma_f16(acc[2 * ntp][0], acc[2 * ntp][1], acc[2 * ntp][2], acc[2 * ntp][3],
                        a0, a1, a2, a3, bb0, bb1);
                mma_f16(acc[2 * ntp + 1][0], acc[2 * ntp + 1][1],
                        acc[2 * ntp + 1][2], acc[2 * ntp + 1][3],
                        a0, a1, a2, a3, bb2, bb3);
            }
        }
    }

    // ---- final epilogue: bias + silu + red.add.v2 scatter into g_msum ------
    {
        const int rA = r0 + qr, rB = rA + 8;
        const int sA = s_src[rA], sB = s_src[rB];
        float* baseA = g_msum + (size_t)sA * D;
        float* baseB = g_msum + (size_t)sB * D;
        #pragma unroll
        for (int nt = 0; nt < 16; ++nt) {
            int c0 = nt * 8 + 2 * qc;
            float v0 = silu(acc[nt][0] + s_b2[c0]);
            float v1 = silu(acc[nt][1] + s_b2[c0 + 1]);
            float v2 = silu(acc[nt][2] + s_b2[c0]);
            float v3 = silu(acc[nt][3] + s_b2[c0 + 1]);
            asm volatile("red.global.add.v2.f32 [%0], {%1,%2};"
                         :: "l"(baseA + c0), "f"(v0), "f"(v1) : "memory");
            asm volatile("red.global.add.v2.f32 [%0], {%1,%2};"
                         :: "l"(baseB + c0), "f"(v2), "f"(v3) : "memory");
        }
        if (qc == 0) {
            atomicAdd(&g_cnt[sA], 1.0f);
            atomicAdd(&g_cnt[sB], 1.0f);
        }
    }
}

// ---------------------------------------------------------------------------
// Kernel 3: node aggregation MLP + residual. 64 nodes/block, 4 warps,
// 625 blocks (exact). Same ldmatrix/f16 pipeline.
// ---------------------------------------------------------------------------
__global__ __launch_bounds__(128, 3) void node_kernel(
    const float* __restrict__ nf,
    const float* __restrict__ b1,
    const float* __restrict__ b2,
    float* __restrict__ out)
{
    extern __shared__ char smem[];
    uint32_t* W = (uint32_t*)smem;
    float* s_inv = (float*)(smem + MISC_OFF);
    float* s_b1  = (float*)(smem + MISC_OFF + 512);
    float* s_b2  = (float*)(smem + MISC_OFF + 1024);
    const uint32_t sb = smem_u32(smem);

    const int tid  = threadIdx.x;
    const int wid  = tid >> 5;
    const int lane = tid & 31;
    const int n0   = blockIdx.x * 64;

    if (tid < 64) s_inv[tid] = 1.0f / fmaxf(g_cnt[n0 + tid], 1.0f);
    s_b1[tid] = b1[tid];
    s_b2[tid] = b2[tid];
    __syncthreads();

    const int lrow  = tid >> 1;          // A staging row 0..63
    const int lhalf = tid & 1;
    const int qr = lane >> 2;
    const int qc = lane & 3;
    const int r0 = wid * 16;             // 0..48

    const uint32_t laneA = sb +
        (((uint32_t)(r0 + (lane & 7) + ((lane >> 3) & 1) * 8) * PADW + (lane >> 4) * 4) << 2);
    const uint32_t laneB = sb +
        (((uint32_t)((lane & 7) + ((lane >> 4) & 1) * 8) * PADW + ((lane >> 3) & 1) * 4) << 2);

    float acc[16][4];
    #pragma unroll
    for (int nt = 0; nt < 16; ++nt)
        #pragma unroll
        for (int j = 0; j < 4; ++j) acc[nt][j] = 0.0f;

    // ---- GEMM1: concat(h, mean) [64 x 256] @ AW1t, 8 k-tiles ---------------
    for (int kt = 0; kt < 8; ++kt) {
        const int b = kt & 1;

        const float* ab = (kt < 4 ? g_h : g_msum)
                          + (size_t)(n0 + lrow) * D + (kt & 3) * 32 + lhalf * 16;
        float inv = (kt < 4) ? 1.0f : s_inv[lrow];
        uint32_t w[8];
        #pragma unroll
        for (int j = 0; j < 4; ++j) {
            float4 v = *(const float4*)(ab + j * 4);
            w[2 * j]     = packh(v.x * inv, v.y * inv);
            w[2 * j + 1] = packh(v.z * inv, v.w * inv);
        }
        uint32_t* ap = W + b * TILE_W + lrow * PADW + lhalf * 8;
        *(uint4*)(ap)     = make_uint4(w[0], w[1], w[2], w[3]);
        *(uint4*)(ap + 4) = make_uint4(w[4], w[5], w[6], w[7]);

        // B staging: 128 rows, one row per thread (16 words)
        const uint32_t* wb = g_aw1t + tid * 128 + kt * 16;
        uint32_t* bp = W + (2 + b) * TILE_W + tid * PADW;
        #pragma unroll
        for (int j = 0; j < 4; ++j)
            *(uint4*)(bp + j * 4) = *(const uint4*)(wb + j * 4);
        __syncthreads();

        const uint32_t aA = laneA + b * TILE_B;
        const uint32_t bA = laneB + (2 + b) * TILE_B;
        #pragma unroll
        for (int ks = 0; ks < 2; ++ks) {
            uint32_t a0, a1, a2, a3;
            ldsm_x4(a0, a1, a2, a3, aA + ks * 32);
            #pragma unroll
            for (int ntp = 0; ntp < 8; ++ntp) {
                uint32_t bb0, bb1, bb2, bb3;
                ldsm_x4(bb0, bb1, bb2, bb3, bA + ks * 32 + ntp * (16 * PADW * 4));
                mma_f16(acc[2 * ntp][0], acc[2 * ntp][1], acc[2 * ntp][2], acc[2 * ntp][3],
                        a0, a1, a2, a3, bb0, bb1);
                mma_f16(acc[2 * ntp + 1][0], acc[2 * ntp + 1][1],
                        acc[2 * ntp + 1][2], acc[2 * ntp + 1][3],
                        a0, a1, a2, a3, bb2, bb3);
            }
        }
    }
    __syncthreads();

    // ---- epilogue1 -> Ms tiles 0-3 (rows 0-63 used) -------------------------
    #pragma unroll
    for (int nt = 0; nt < 16; ++nt) {
        int c0 = nt * 8 + 2 * qc;
        int wbase = (nt >> 2) * TILE_W + (nt & 3) * 4 + qc;
        float v0 = silu(acc[nt][0] + s_b1[c0]);
        float v1 = silu(acc[nt][1] + s_b1[c0 + 1]);
        float v2 = silu(acc[nt][2] + s_b1[c0]);
        float v3 = silu(acc[nt][3] + s_b1[c0 + 1]);
        W[wbase + (r0 + qr)     * PADW] = packh(v0, v1);
        W[wbase + (r0 + qr + 8) * PADW] = packh(v2, v3);
        acc[nt][0] = 0.f; acc[nt][1] = 0.f; acc[nt][2] = 0.f; acc[nt][3] = 0.f;
    }

    // ---- GEMM2: [64 x 128] @ AW2t, 4 k-tiles --------------------------------
    for (int kt = 0; kt < 4; ++kt) {
        const int b = kt & 1;
        const uint32_t* wb = g_aw2t + tid * 64 + kt * 16;
        uint32_t* bp = W + (4 + b) * TILE_W + tid * PADW;
        #pragma unroll
        for (int j = 0; j < 4; ++j)
            *(uint4*)(bp + j * 4) = *(const uint4*)(wb + j * 4);
        __syncthreads();

        const uint32_t aA = laneA + kt * TILE_B;
        const uint32_t bA = laneB + (4 + b) * TILE_B;
        #pragma unroll
        for (int ks = 0; ks < 2; ++ks) {
            uint32_t a0, a1, a2, a3;
            ldsm_x4(a0, a1, a2, a3, aA + ks * 32);
            #pragma unroll
            for (int ntp = 0; ntp < 8; ++ntp) {
                uint32_t bb0, bb1, bb2, bb3;
                ldsm_x4(bb0, bb1, bb2, bb3, bA + ks * 32 + ntp * (16 * PADW * 4));
                mma_f16(acc[2 * ntp][0], acc[2 * ntp][1], acc[2 * ntp][2], acc[2 * ntp][3],
                        a0, a1, a2, a3, bb0, bb1);
                mma_f16(acc[2 * ntp + 1][0], acc[2 * ntp + 1][1],
                        acc[2 * ntp + 1][2], acc[2 * ntp + 1][3],
                        a0, a1, a2, a3, bb2, bb3);
            }
        }
    }

    // ---- final: bias + silu + residual -> out --------------------------------
    {
        const int nA = n0 + r0 + qr, nB = nA + 8;
        #pragma unroll
        for (int nt = 0; nt < 16; ++nt) {
            int c0 = nt * 8 + 2 * qc;
            float2 rA = *(const float2*)(nf + (size_t)nA * D + c0);
            float2 oA;
            oA.x = rA.x + silu(acc[nt][0] + s_b2[c0]);
            oA.y = rA.y + silu(acc[nt][1] + s_b2[c0 + 1]);
            *(float2*)(out + (size_t)nA * D + c0) = oA;
            float2 rB = *(const float2*)(nf + (size_t)nB * D + c0);
            float2 oB;
            oB.x = rB.x + silu(acc[nt][2] + s_b2[c0]);
            oB.y = rB.y + silu(acc[nt][3] + s_b2[c0 + 1]);
            *(float2*)(out + (size_t)nB * D + c0) = oB;
        }
    }
}

// ---------------------------------------------------------------------------
extern "C" void kernel_launch(void* const* d_in, const int* in_sizes, int n_in,
                              void* d_out, int out_size)
{
    const float* nf    = (const float*)d_in[0];
    const float* ef    = (const float*)d_in[1];
    const float* gamma = (const float*)d_in[2];
    const float* beta  = (const float*)d_in[3];
    const float* mw1   = (const float*)d_in[4];
    const float* mb1   = (const float*)d_in[5];
    const float* mw2   = (const float*)d_in[6];
    const float* mb2   = (const float*)d_in[7];
    const float* aw1   = (const float*)d_in[8];
    const float* ab1   = (const float*)d_in[9];
    const float* aw2   = (const float*)d_in[10];
    const float* ab2   = (const float*)d_in[11];
    const int*   eidx  = (const int*)d_in[12];
    float*       out   = (float*)d_out;

    const int* src = eidx;
    const int* dst = eidx + N_EDGES;

    cudaFuncSetAttribute(edge_kernel, cudaFuncAttributeMaxDynamicSharedMemorySize, SMEM_SZ);
    cudaFuncSetAttribute(node_kernel, cudaFuncAttributeMaxDynamicSharedMemorySize, SMEM_SZ);

    prep_weights<<<224, 256>>>(mw1, mw2, aw1, aw2);
    ln_kernel<<<N_NODES / 8, 256>>>(nf, gamma, beta);
    edge_kernel<<<N_EDGES / 128, 256, SMEM_SZ>>>(ef, mb1, mb2, src, dst);
    node_kernel<<<N_NODES / 64, 128, SMEM_SZ>>>(nf, ab1, ab2, out);
}

// round 16
// speedup vs baseline: 1.8074x; 1.2189x over previous
#include <cuda_runtime.h>
#include <cstdint>

// ---------------------------------------------------------------------------
// ENGNLayer on GB300: LN(fp16 out) -> edge MLP (mma.sync f16 + ldmatrix +
// cp.async 3-stage pipeline) + scatter -> node MLP + residual.
// N=40000, E=640000, D=128.
// ---------------------------------------------------------------------------

#define N_NODES 40000
#define N_EDGES 640000
#define D 128
#define LN_EPS 1e-5f

// Device scratch (allocation-free rule)
__device__ uint32_t g_hh[N_NODES * 64];    // LayerNorm output, f16x2
__device__ uint32_t g_efh[N_EDGES * 64];   // edge features, f16x2
__device__ float    g_msum[N_NODES * D];   // scatter sum (fp32 atomics)
__device__ float    g_cnt[N_NODES];        // scatter count
__device__ uint32_t g_w1t[128 * 192];      // msg_w1^T  f16x2  [n][k/2]
__device__ uint32_t g_w2t[128 * 64];       // msg_w2^T  f16x2
__device__ uint32_t g_aw1t[128 * 128];     // agg_w1^T  f16x2
__device__ uint32_t g_aw2t[128 * 64];      // agg_w2^T  f16x2

__device__ __forceinline__ float silu(float x) { return x / (1.0f + __expf(-x)); }

__device__ __forceinline__ uint32_t packh(float lo, float hi) {
    uint32_t r;
    asm("cvt.rn.f16x2.f32 %0, %1, %2;" : "=r"(r) : "f"(hi), "f"(lo));
    return r;
}

__device__ __forceinline__ uint32_t smem_u32(const void* p) {
    uint32_t a;
    asm("{ .reg .u64 t; cvta.to.shared.u64 t, %1; cvt.u32.u64 %0, t; }" : "=r"(a) : "l"(p));
    return a;
}

__device__ __forceinline__ void mma_f16(
    float& c0, float& c1, float& c2, float& c3,
    uint32_t a0, uint32_t a1, uint32_t a2, uint32_t a3,
    uint32_t b0, uint32_t b1)
{
    asm volatile(
        "mma.sync.aligned.m16n8k16.row.col.f32.f16.f16.f32 "
        "{%0,%1,%2,%3}, {%4,%5,%6,%7}, {%8,%9}, {%0,%1,%2,%3};"
        : "+f"(c0), "+f"(c1), "+f"(c2), "+f"(c3)
        : "r"(a0), "r"(a1), "r"(a2), "r"(a3), "r"(b0), "r"(b1));
}

__device__ __forceinline__ void ldsm_x4(
    uint32_t& r0, uint32_t& r1, uint32_t& r2, uint32_t& r3, uint32_t addr)
{
    asm volatile("ldmatrix.sync.aligned.m8n8.x4.shared.b16 {%0,%1,%2,%3}, [%4];"
                 : "=r"(r0), "=r"(r1), "=r"(r2), "=r"(r3) : "r"(addr));
}

__device__ __forceinline__ void cpa16(uint32_t dst, const void* src) {
    asm volatile("cp.async.cg.shared.global [%0], [%1], 16;" :: "r"(dst), "l"(src) : "memory");
}
#define CPA_COMMIT() asm volatile("cp.async.commit_group;" ::: "memory")
#define CPA_WAIT1()  asm volatile("cp.async.wait_group 1;" ::: "memory")
#define CPA_WAIT0()  asm volatile("cp.async.wait_group 0;" ::: "memory")

// ---------------------------------------------------------------------------
// Tile geometry: tile = [128 rows][32 f16 = 16 words], rows padded to 20 words.
// Edge smem: slots 0-2 A ring, 3-5 B ring, 6-9 m1 tiles, misc after.
// ---------------------------------------------------------------------------
#define PADW 20
#define TILE_W (128 * PADW)
#define TILE_B (TILE_W * 4)              // 10240 bytes
#define EDGE_MISC (10 * TILE_B)          // 102400
#define EDGE_SMEM (EDGE_MISC + 2048)     // 104448
#define NODE_MISC (6 * TILE_B)           // 61440
#define NODE_SMEM (NODE_MISC + 2048)     // 63488

// ---------------------------------------------------------------------------
// Kernel 0a: transpose + f16-pack weights.
// ---------------------------------------------------------------------------
__global__ __launch_bounds__(256) void prep_weights(
    const float* __restrict__ w1,  const float* __restrict__ w2,
    const float* __restrict__ aw1, const float* __restrict__ aw2)
{
    int i = blockIdx.x * 256 + threadIdx.x;
    if (i < 24576) {                       // w1t: [128][192]
        int n = i / 192, wk = i % 192;
        g_w1t[i] = packh(w1[(2 * wk) * 128 + n], w1[(2 * wk + 1) * 128 + n]);
    } else if (i < 32768) {                // w2t: [128][64]
        int j = i - 24576, n = j / 64, wk = j % 64;
        g_w2t[j] = packh(w2[(2 * wk) * 128 + n], w2[(2 * wk + 1) * 128 + n]);
    } else if (i < 49152) {                // aw1t: [128][128]
        int j = i - 32768, n = j / 128, wk = j % 128;
        g_aw1t[j] = packh(aw1[(2 * wk) * 128 + n], aw1[(2 * wk + 1) * 128 + n]);
    } else if (i < 57344) {                // aw2t: [128][64]
        int j = i - 49152, n = j / 64, wk = j % 64;
        g_aw2t[j] = packh(aw2[(2 * wk) * 128 + n], aw2[(2 * wk + 1) * 128 + n]);
    }
}

// ---------------------------------------------------------------------------
// Kernel 0b: stream-convert edge features to f16. One float4 per thread.
// ---------------------------------------------------------------------------
__global__ __launch_bounds__(256) void ef2h_kernel(const float* __restrict__ ef)
{
    size_t i = (size_t)blockIdx.x * 256 + threadIdx.x;
    float4 v = ((const float4*)ef)[i];
    uint2 w;
    w.x = packh(v.x, v.y);
    w.y = packh(v.z, v.w);
    ((uint2*)g_efh)[i] = w;
}

// ---------------------------------------------------------------------------
// Kernel 1: LayerNorm -> g_hh (f16) + zero scatter buffers.
// ---------------------------------------------------------------------------
__global__ __launch_bounds__(256) void ln_kernel(
    const float* __restrict__ nf,
    const float* __restrict__ gamma,
    const float* __restrict__ beta)
{
    int node = blockIdx.x * 8 + (threadIdx.x >> 5);
    int lane = threadIdx.x & 31;
    if (node >= N_NODES) return;

    float4 v = ((const float4*)(nf + (size_t)node * D))[lane];
    float s  = v.x + v.y + v.z + v.w;
    float sq = v.x * v.x + v.y * v.y + v.z * v.z + v.w * v.w;
    #pragma unroll
    for (int off = 16; off; off >>= 1) {
        s  += __shfl_xor_sync(0xFFFFFFFFu, s, off);
        sq += __shfl_xor_sync(0xFFFFFFFFu, sq, off);
    }
    float mu = s * (1.0f / D);
    float var = sq * (1.0f / D) - mu * mu;
    float rstd = rsqrtf(var + LN_EPS);

    float4 g = ((const float4*)gamma)[lane];
    float4 b = ((const float4*)beta)[lane];
    float hx = (v.x - mu) * rstd * g.x + b.x;
    float hy = (v.y - mu) * rstd * g.y + b.y;
    float hz = (v.z - mu) * rstd * g.z + b.z;
    float hw = (v.w - mu) * rstd * g.w + b.w;

    uint2 hwv;
    hwv.x = packh(hx, hy);
    hwv.y = packh(hz, hw);
    ((uint2*)(g_hh + (size_t)node * 64))[lane] = hwv;
    ((float4*)(g_msum + (size_t)node * D))[lane] = make_float4(0.f, 0.f, 0.f, 0.f);
    if (lane == 0) g_cnt[node] = 0.0f;
}

// ---------------------------------------------------------------------------
// Shared MMA tile body: 2 k-steps x 8 n-pairs, ldmatrix + m16n8k16.
// ---------------------------------------------------------------------------
__device__ __forceinline__ void mma_tile(
    float (&acc)[16][4], uint32_t aAddr, uint32_t bAddr)
{
    #pragma unroll
    for (int ks = 0; ks < 2; ++ks) {
        uint32_t a0, a1, a2, a3;
        ldsm_x4(a0, a1, a2, a3, aAddr + ks * 32);
        #pragma unroll
        for (int ntp = 0; ntp < 8; ++ntp) {
            uint32_t b0, b1, b2, b3;
            ldsm_x4(b0, b1, b2, b3, bAddr + ks * 32 + ntp * (16 * PADW * 4));
            mma_f16(acc[2 * ntp][0], acc[2 * ntp][1], acc[2 * ntp][2], acc[2 * ntp][3],
                    a0, a1, a2, a3, b0, b1);
            mma_f16(acc[2 * ntp + 1][0], acc[2 * ntp + 1][1],
                    acc[2 * ntp + 1][2], acc[2 * ntp + 1][3],
                    a0, a1, a2, a3, b2, b3);
        }
    }
}

// ---------------------------------------------------------------------------
// Kernel 2: edge MLP + scatter.  128 edges/block, 8 warps.
// 16 pipeline tiles: t 0..11 = GEMM1 (A gather + W1 slice), 12..15 = W2 slices.
// 3-deep cp.async ring: tile t staged at iteration t-2.
// ---------------------------------------------------------------------------
__global__ __launch_bounds__(256, 2) void edge_kernel(
    const float* __restrict__ b1,
    const float* __restrict__ b2,
    const int*  __restrict__ src,
    const int*  __restrict__ dst)
{
    extern __shared__ char smem[];
    uint32_t* W = (uint32_t*)smem;
    int*   s_src = (int*)(smem + EDGE_MISC);
    int*   s_dst = (int*)(smem + EDGE_MISC + 512);
    float* s_b1  = (float*)(smem + EDGE_MISC + 1024);
    float* s_b2  = (float*)(smem + EDGE_MISC + 1536);
    const uint32_t sb = smem_u32(smem);

    const int tid  = threadIdx.x;
    const int wid  = tid >> 5;
    const int lane = tid & 31;
    const int e0   = blockIdx.x * 128;

    if (tid < 128) { s_src[tid] = src[e0 + tid];             s_b1[tid] = b1[tid]; }
    else           { s_dst[tid - 128] = dst[e0 + tid - 128]; s_b2[tid - 128] = b2[tid - 128]; }
    __syncthreads();

    const int lrow  = tid >> 1;
    const int lhalf = tid & 1;
    const int qr = lane >> 2;
    const int qc = lane & 3;
    const int r0 = wid * 16;

    const uint32_t laneA = sb +
        (((uint32_t)(r0 + (lane & 7) + ((lane >> 3) & 1) * 8) * PADW + (lane >> 4) * 4) << 2);
    const uint32_t laneB = sb +
        (((uint32_t)((lane & 7) + ((lane >> 4) & 1) * 8) * PADW + ((lane >> 3) & 1) * 4) << 2);

    const uint32_t stageOff = ((uint32_t)lrow * PADW + lhalf * 8) << 2;

    // stage tile t into ring slot t%3 (A) / 3+t%3 (B); one commit group per tile
    auto stage = [&](int t) {
        uint32_t bdst = sb + (3 + (t % 3)) * TILE_B + stageOff;
        if (t < 12) {
            const uint32_t* as;
            if (t < 4)      as = g_hh  + (size_t)s_src[lrow] * 64 + t * 16;
            else if (t < 8) as = g_hh  + (size_t)s_dst[lrow] * 64 + (t - 4) * 16;
            else            as = g_efh + (size_t)(e0 + lrow) * 64 + (t - 8) * 16;
            as += lhalf * 8;
            uint32_t adst = sb + (t % 3) * TILE_B + stageOff;
            cpa16(adst, as); cpa16(adst + 16, as + 4);
            const uint32_t* ws = g_w1t + lrow * 192 + t * 16 + lhalf * 8;
            cpa16(bdst, ws); cpa16(bdst + 16, ws + 4);
        } else {
            const uint32_t* ws = g_w2t + lrow * 64 + (t - 12) * 16 + lhalf * 8;
            cpa16(bdst, ws); cpa16(bdst + 16, ws + 4);
        }
        CPA_COMMIT();
    };

    float acc[16][4];
    #pragma unroll
    for (int nt = 0; nt < 16; ++nt)
        #pragma unroll
        for (int j = 0; j < 4; ++j) acc[nt][j] = 0.0f;

    // prologue: tiles 0,1 in flight
    stage(0);
    stage(1);

    // ---------------- GEMM1: 12 k-tiles ----------------
    for (int kt = 0; kt < 12; ++kt) {
        CPA_WAIT1();          // tile kt landed; kt+1 may still fly
        __syncthreads();      // all warps past compute(kt-1) before slot reuse
        stage(kt + 2);        // tiles 2..13
        mma_tile(acc, laneA + (kt % 3) * TILE_B, laneB + (3 + (kt % 3)) * TILE_B);
    }

    // ---- epilogue1: bias + silu -> f16 -> m1 tiles 6..9 (warp-local rows) --
    #pragma unroll
    for (int nt = 0; nt < 16; ++nt) {
        int c0 = nt * 8 + 2 * qc;
        int wbase = (6 + (nt >> 2)) * TILE_W + (nt & 3) * 4 + qc;
        float v0 = silu(acc[nt][0] + s_b1[c0]);
        float v1 = silu(acc[nt][1] + s_b1[c0 + 1]);
        float v2 = silu(acc[nt][2] + s_b1[c0]);
        float v3 = silu(acc[nt][3] + s_b1[c0 + 1]);
        W[wbase + (r0 + qr)     * PADW] = packh(v0, v1);
        W[wbase + (r0 + qr + 8) * PADW] = packh(v2, v3);
        acc[nt][0] = 0.f; acc[nt][1] = 0.f; acc[nt][2] = 0.f; acc[nt][3] = 0.f;
    }
    __syncwarp();   // own-warp STS -> ldmatrix ordering for m1

    // ---------------- GEMM2: 4 k-tiles (pipeline tiles 12..15) --------------
    for (int kt = 0; kt < 4; ++kt) {
        if (kt == 3) { CPA_WAIT0(); } else { CPA_WAIT1(); }
        __syncthreads();
        if (kt < 2) stage(14 + kt);
        mma_tile(acc, laneA + (6 + kt) * TILE_B, laneB + (3 + ((12 + kt) % 3)) * TILE_B);
    }

    // ---- final epilogue: bias + silu + red.add.v2 scatter into g_msum ------
    {
        const int rA = r0 + qr, rB = rA + 8;
        const int sA = s_src[rA], sB = s_src[rB];
        float* baseA = g_msum + (size_t)sA * D;
        float* baseB = g_msum + (size_t)sB * D;
        #pragma unroll
        for (int nt = 0; nt < 16; ++nt) {
            int c0 = nt * 8 + 2 * qc;
            float v0 = silu(acc[nt][0] + s_b2[c0]);
            float v1 = silu(acc[nt][1] + s_b2[c0 + 1]);
            float v2 = silu(acc[nt][2] + s_b2[c0]);
            float v3 = silu(acc[nt][3] + s_b2[c0 + 1]);
            asm volatile("red.global.add.v2.f32 [%0], {%1,%2};"
                         :: "l"(baseA + c0), "f"(v0), "f"(v1) : "memory");
            asm volatile("red.global.add.v2.f32 [%0], {%1,%2};"
                         :: "l"(baseB + c0), "f"(v2), "f"(v3) : "memory");
        }
        if (qc == 0) {
            atomicAdd(&g_cnt[sA], 1.0f);
            atomicAdd(&g_cnt[sB], 1.0f);
        }
    }
}

// ---------------------------------------------------------------------------
// Kernel 3: node aggregation MLP + residual. 64 nodes/block, 4 warps.
// h-half of A copied straight from g_hh; mean-half loaded fp32 + scaled + packed.
// ---------------------------------------------------------------------------
__global__ __launch_bounds__(128, 3) void node_kernel(
    const float* __restrict__ nf,
    const float* __restrict__ b1,
    const float* __restrict__ b2,
    float* __restrict__ out)
{
    extern __shared__ char smem[];
    uint32_t* W = (uint32_t*)smem;
    float* s_inv = (float*)(smem + NODE_MISC);
    float* s_b1  = (float*)(smem + NODE_MISC + 512);
    float* s_b2  = (float*)(smem + NODE_MISC + 1024);
    const uint32_t sb = smem_u32(smem);

    const int tid  = threadIdx.x;
    const int wid  = tid >> 5;
    const int lane = tid & 31;
    const int n0   = blockIdx.x * 64;

    if (tid < 64) s_inv[tid] = 1.0f / fmaxf(g_cnt[n0 + tid], 1.0f);
    s_b1[tid] = b1[tid];
    s_b2[tid] = b2[tid];
    __syncthreads();

    const int lrow  = tid >> 1;
    const int lhalf = tid & 1;
    const int qr = lane >> 2;
    const int qc = lane & 3;
    const int r0 = wid * 16;

    const uint32_t laneA = sb +
        (((uint32_t)(r0 + (lane & 7) + ((lane >> 3) & 1) * 8) * PADW + (lane >> 4) * 4) << 2);
    const uint32_t laneB = sb +
        (((uint32_t)((lane & 7) + ((lane >> 4) & 1) * 8) * PADW + ((lane >> 3) & 1) * 4) << 2);

    float acc[16][4];
    #pragma unroll
    for (int nt = 0; nt < 16; ++nt)
        #pragma unroll
        for (int j = 0; j < 4; ++j) acc[nt][j] = 0.0f;

    // ---- GEMM1: concat(h, mean) [64 x 256] @ AW1t, 8 k-tiles ---------------
    for (int kt = 0; kt < 8; ++kt) {
        const int b = kt & 1;
        uint32_t* ap = W + b * TILE_W + lrow * PADW + lhalf * 8;

        if (kt < 4) {
            const uint32_t* as = g_hh + (size_t)(n0 + lrow) * 64 + kt * 16 + lhalf * 8;
            *(uint4*)(ap)     = *(const uint4*)(as);
            *(uint4*)(ap + 4) = *(const uint4*)(as + 4);
        } else {
            const float* ab = g_msum + (size_t)(n0 + lrow) * D + (kt & 3) * 32 + lhalf * 16;
            float inv = s_inv[lrow];
            uint32_t w[8];
            #pragma unroll
            for (int j = 0; j < 4; ++j) {
                float4 v = *(const float4*)(ab + j * 4);
                w[2 * j]     = packh(v.x * inv, v.y * inv);
                w[2 * j + 1] = packh(v.z * inv, v.w * inv);
            }
            *(uint4*)(ap)     = make_uint4(w[0], w[1], w[2], w[3]);
            *(uint4*)(ap + 4) = make_uint4(w[4], w[5], w[6], w[7]);
        }

        const uint32_t* wb = g_aw1t + tid * 128 + kt * 16;
        uint32_t* bp = W + (2 + b) * TILE_W + tid * PADW;
        #pragma unroll
        for (int j = 0; j < 4; ++j)
            *(uint4*)(bp + j * 4) = *(const uint4*)(wb + j * 4);
        __syncthreads();

        mma_tile(acc, laneA + b * TILE_B, laneB + (2 + b) * TILE_B);
        __syncthreads();
    }

    // ---- epilogue1 -> m1 tiles 0-3 ------------------------------------------
    #pragma unroll
    for (int nt = 0; nt < 16; ++nt) {
        int c0 = nt * 8 + 2 * qc;
        int wbase = (nt >> 2) * TILE_W + (nt & 3) * 4 + qc;
        float v0 = silu(acc[nt][0] + s_b1[c0]);
        float v1 = silu(acc[nt][1] + s_b1[c0 + 1]);
        float v2 = silu(acc[nt][2] + s_b1[c0]);
        float v3 = silu(acc[nt][3] + s_b1[c0 + 1]);
        W[wbase + (r0 + qr)     * PADW] = packh(v0, v1);
        W[wbase + (r0 + qr + 8) * PADW] = packh(v2, v3);
        acc[nt][0] = 0.f; acc[nt][1] = 0.f; acc[nt][2] = 0.f; acc[nt][3] = 0.f;
    }
    __syncthreads();

    // ---- GEMM2: [64 x 128] @ AW2t, 4 k-tiles --------------------------------
    for (int kt = 0; kt < 4; ++kt) {
        const int b = kt & 1;
        const uint32_t* wb = g_aw2t + tid * 64 + kt * 16;
        uint32_t* bp = W + (4 + b) * TILE_W + tid * PADW;
        #pragma unroll
        for (int j = 0; j < 4; ++j)
            *(uint4*)(bp + j * 4) = *(const uint4*)(wb + j * 4);
        __syncthreads();

        mma_tile(acc, laneA + kt * TILE_B, laneB + (4 + b) * TILE_B);
        __syncthreads();
    }

    // ---- final: bias + silu + residual -> out --------------------------------
    {
        const int nA = n0 + r0 + qr, nB = nA + 8;
        #pragma unroll
        for (int nt = 0; nt < 16; ++nt) {
            int c0 = nt * 8 + 2 * qc;
            float2 rA = *(const float2*)(nf + (size_t)nA * D + c0);
            float2 oA;
            oA.x = rA.x + silu(acc[nt][0] + s_b2[c0]);
            oA.y = rA.y + silu(acc[nt][1] + s_b2[c0 + 1]);
            *(float2*)(out + (size_t)nA * D + c0) = oA;
            float2 rB = *(const float2*)(nf + (size_t)nB * D + c0);
            float2 oB;
            oB.x = rB.x + silu(acc[nt][2] + s_b2[c0]);
            oB.y = rB.y + silu(acc[nt][3] + s_b2[c0 + 1]);
            *(float2*)(out + (size_t)nB * D + c0) = oB;
        }
    }
}

// ---------------------------------------------------------------------------
extern "C" void kernel_launch(void* const* d_in, const int* in_sizes, int n_in,
                              void* d_out, int out_size)
{
    const float* nf    = (const float*)d_in[0];
    const float* ef    = (const float*)d_in[1];
    const float* gamma = (const float*)d_in[2];
    const float* beta  = (const float*)d_in[3];
    const float* mw1   = (const float*)d_in[4];
    const float* mb1   = (const float*)d_in[5];
    const float* mw2   = (const float*)d_in[6];
    const float* mb2   = (const float*)d_in[7];
    const float* aw1   = (const float*)d_in[8];
    const float* ab1   = (const float*)d_in[9];
    const float* aw2   = (const float*)d_in[10];
    const float* ab2   = (const float*)d_in[11];
    const int*   eidx  = (const int*)d_in[12];
    float*       out   = (float*)d_out;

    const int* src = eidx;
    const int* dst = eidx + N_EDGES;

    cudaFuncSetAttribute(edge_kernel, cudaFuncAttributeMaxDynamicSharedMemorySize, EDGE_SMEM);
    cudaFuncSetAttribute(node_kernel, cudaFuncAttributeMaxDynamicSharedMemorySize, NODE_SMEM);

    prep_weights<<<224, 256>>>(mw1, mw2, aw1, aw2);
    ef2h_kernel<<<(N_EDGES * (D / 4)) / 256, 256>>>(ef);
    ln_kernel<<<N_NODES / 8, 256>>>(nf, gamma, beta);
    edge_kernel<<<N_EDGES / 128, 256, EDGE_SMEM>>>(mb1, mb2, src, dst);
    node_kernel<<<N_NODES / 64, 128, NODE_SMEM>>>(nf, ab1, ab2, out);
}

// round 17
// speedup vs baseline: 1.8358x; 1.0157x over previous
#include <cuda_runtime.h>
#include <cstdint>

// ---------------------------------------------------------------------------
// ENGNLayer on GB300: LN(fp16 out) -> edge MLP (mma.sync f16, 32x64 warp
// tiles, ldmatrix, cp.async 3-stage ring) + scatter -> node MLP + residual.
// N=40000, E=640000, D=128.
// ---------------------------------------------------------------------------

#define N_NODES 40000
#define N_EDGES 640000
#define D 128
#define LN_EPS 1e-5f

// Device scratch (allocation-free rule)
__device__ uint32_t g_hh[N_NODES * 64];    // LayerNorm output, f16x2
__device__ uint32_t g_efh[N_EDGES * 64];   // edge features, f16x2
__device__ float    g_msum[N_NODES * D];   // scatter sum (fp32 atomics)
__device__ float    g_cnt[N_NODES];        // scatter count
__device__ uint32_t g_w1t[128 * 192];      // msg_w1^T  f16x2  [n][k/2]
__device__ uint32_t g_w2t[128 * 64];       // msg_w2^T  f16x2
__device__ uint32_t g_aw1t[128 * 128];     // agg_w1^T  f16x2
__device__ uint32_t g_aw2t[128 * 64];      // agg_w2^T  f16x2

__device__ __forceinline__ float silu(float x) { return x / (1.0f + __expf(-x)); }

__device__ __forceinline__ uint32_t packh(float lo, float hi) {
    uint32_t r;
    asm("cvt.rn.f16x2.f32 %0, %1, %2;" : "=r"(r) : "f"(hi), "f"(lo));
    return r;
}

__device__ __forceinline__ uint32_t smem_u32(const void* p) {
    uint32_t a;
    asm("{ .reg .u64 t; cvta.to.shared.u64 t, %1; cvt.u32.u64 %0, t; }" : "=r"(a) : "l"(p));
    return a;
}

__device__ __forceinline__ void mma_f16(
    float& c0, float& c1, float& c2, float& c3,
    uint32_t a0, uint32_t a1, uint32_t a2, uint32_t a3,
    uint32_t b0, uint32_t b1)
{
    asm volatile(
        "mma.sync.aligned.m16n8k16.row.col.f32.f16.f16.f32 "
        "{%0,%1,%2,%3}, {%4,%5,%6,%7}, {%8,%9}, {%0,%1,%2,%3};"
        : "+f"(c0), "+f"(c1), "+f"(c2), "+f"(c3)
        : "r"(a0), "r"(a1), "r"(a2), "r"(a3), "r"(b0), "r"(b1));
}

__device__ __forceinline__ void ldsm_x4(
    uint32_t& r0, uint32_t& r1, uint32_t& r2, uint32_t& r3, uint32_t addr)
{
    asm volatile("ldmatrix.sync.aligned.m8n8.x4.shared.b16 {%0,%1,%2,%3}, [%4];"
                 : "=r"(r0), "=r"(r1), "=r"(r2), "=r"(r3) : "r"(addr));
}

__device__ __forceinline__ void cpa16(uint32_t dst, const void* src) {
    asm volatile("cp.async.cg.shared.global [%0], [%1], 16;" :: "r"(dst), "l"(src) : "memory");
}
#define CPA_COMMIT() asm volatile("cp.async.commit_group;" ::: "memory")
#define CPA_WAIT1()  asm volatile("cp.async.wait_group 1;" ::: "memory")
#define CPA_WAIT0()  asm volatile("cp.async.wait_group 0;" ::: "memory")

// ---------------------------------------------------------------------------
// Tile geometry: tile = [128 rows][32 f16 = 16 words], rows padded to 20 words.
// Edge smem: slots 0-2 A ring, 3-5 B ring, 6-9 m1 tiles, misc after.
// ---------------------------------------------------------------------------
#define PADW 20
#define TILE_W (128 * PADW)
#define TILE_B (TILE_W * 4)              // 10240 bytes
#define EDGE_MISC (10 * TILE_B)          // 102400
#define EDGE_SMEM (EDGE_MISC + 2048)     // 104448
#define NODE_MISC (6 * TILE_B)           // 61440
#define NODE_SMEM (NODE_MISC + 2048)     // 63488

// ---------------------------------------------------------------------------
// Kernel 0a: transpose + f16-pack weights.
// ---------------------------------------------------------------------------
__global__ __launch_bounds__(256) void prep_weights(
    const float* __restrict__ w1,  const float* __restrict__ w2,
    const float* __restrict__ aw1, const float* __restrict__ aw2)
{
    int i = blockIdx.x * 256 + threadIdx.x;
    if (i < 24576) {                       // w1t: [128][192]
        int n = i / 192, wk = i % 192;
        g_w1t[i] = packh(w1[(2 * wk) * 128 + n], w1[(2 * wk + 1) * 128 + n]);
    } else if (i < 32768) {                // w2t: [128][64]
        int j = i - 24576, n = j / 64, wk = j % 64;
        g_w2t[j] = packh(w2[(2 * wk) * 128 + n], w2[(2 * wk + 1) * 128 + n]);
    } else if (i < 49152) {                // aw1t: [128][128]
        int j = i - 32768, n = j / 128, wk = j % 128;
        g_aw1t[j] = packh(aw1[(2 * wk) * 128 + n], aw1[(2 * wk + 1) * 128 + n]);
    } else if (i < 57344) {                // aw2t: [128][64]
        int j = i - 49152, n = j / 64, wk = j % 64;
        g_aw2t[j] = packh(aw2[(2 * wk) * 128 + n], aw2[(2 * wk + 1) * 128 + n]);
    }
}

// ---------------------------------------------------------------------------
// Kernel 0b: stream-convert edge features to f16.
// ---------------------------------------------------------------------------
__global__ __launch_bounds__(256) void ef2h_kernel(const float* __restrict__ ef)
{
    size_t i = (size_t)blockIdx.x * 256 + threadIdx.x;
    float4 v = ((const float4*)ef)[i];
    uint2 w;
    w.x = packh(v.x, v.y);
    w.y = packh(v.z, v.w);
    ((uint2*)g_efh)[i] = w;
}

// ---------------------------------------------------------------------------
// Kernel 1: LayerNorm -> g_hh (f16) + zero scatter buffers.
// ---------------------------------------------------------------------------
__global__ __launch_bounds__(256) void ln_kernel(
    const float* __restrict__ nf,
    const float* __restrict__ gamma,
    const float* __restrict__ beta)
{
    int node = blockIdx.x * 8 + (threadIdx.x >> 5);
    int lane = threadIdx.x & 31;
    if (node >= N_NODES) return;

    float4 v = ((const float4*)(nf + (size_t)node * D))[lane];
    float s  = v.x + v.y + v.z + v.w;
    float sq = v.x * v.x + v.y * v.y + v.z * v.z + v.w * v.w;
    #pragma unroll
    for (int off = 16; off; off >>= 1) {
        s  += __shfl_xor_sync(0xFFFFFFFFu, s, off);
        sq += __shfl_xor_sync(0xFFFFFFFFu, sq, off);
    }
    float mu = s * (1.0f / D);
    float var = sq * (1.0f / D) - mu * mu;
    float rstd = rsqrtf(var + LN_EPS);

    float4 g = ((const float4*)gamma)[lane];
    float4 b = ((const float4*)beta)[lane];
    float hx = (v.x - mu) * rstd * g.x + b.x;
    float hy = (v.y - mu) * rstd * g.y + b.y;
    float hz = (v.z - mu) * rstd * g.z + b.z;
    float hw = (v.w - mu) * rstd * g.w + b.w;

    uint2 hwv;
    hwv.x = packh(hx, hy);
    hwv.y = packh(hz, hw);
    ((uint2*)(g_hh + (size_t)node * 64))[lane] = hwv;
    ((float4*)(g_msum + (size_t)node * D))[lane] = make_float4(0.f, 0.f, 0.f, 0.f);
    if (lane == 0) g_cnt[node] = 0.0f;
}

// ---------------------------------------------------------------------------
// 32x64 warp-tile MMA body: 2 k-steps x (2 A-ldsm + 4 B-ldsm + 16 MMA).
// acc[g] with g = mrow*8 + n8:  row = r0 + mrow*16 + qr (+8),
//                               col = n0c + n8*8 + 2qc (+1).
// ---------------------------------------------------------------------------
__device__ __forceinline__ void mma_tile32(
    float (&acc)[16][4], uint32_t aAddr, uint32_t bAddr)
{
    #pragma unroll
    for (int ks = 0; ks < 2; ++ks) {
        uint32_t a0, a1, a2, a3, a4, a5, a6, a7;
        ldsm_x4(a0, a1, a2, a3, aAddr + ks * 32);
        ldsm_x4(a4, a5, a6, a7, aAddr + 16 * PADW * 4 + ks * 32);
        #pragma unroll
        for (int nb = 0; nb < 4; ++nb) {
            uint32_t b0, b1, b2, b3;
            ldsm_x4(b0, b1, b2, b3, bAddr + ks * 32 + nb * (16 * PADW * 4));
            mma_f16(acc[2 * nb][0], acc[2 * nb][1], acc[2 * nb][2], acc[2 * nb][3],
                    a0, a1, a2, a3, b0, b1);
            mma_f16(acc[2 * nb + 1][0], acc[2 * nb + 1][1],
                    acc[2 * nb + 1][2], acc[2 * nb + 1][3],
                    a0, a1, a2, a3, b2, b3);
            mma_f16(acc[8 + 2 * nb][0], acc[8 + 2 * nb][1],
                    acc[8 + 2 * nb][2], acc[8 + 2 * nb][3],
                    a4, a5, a6, a7, b0, b1);
            mma_f16(acc[8 + 2 * nb + 1][0], acc[8 + 2 * nb + 1][1],
                    acc[8 + 2 * nb + 1][2], acc[8 + 2 * nb + 1][3],
                    a4, a5, a6, a7, b2, b3);
        }
    }
}

// 16x128 warp-tile body (node kernel, 4 warps).
__device__ __forceinline__ void mma_tile(
    float (&acc)[16][4], uint32_t aAddr, uint32_t bAddr)
{
    #pragma unroll
    for (int ks = 0; ks < 2; ++ks) {
        uint32_t a0, a1, a2, a3;
        ldsm_x4(a0, a1, a2, a3, aAddr + ks * 32);
        #pragma unroll
        for (int ntp = 0; ntp < 8; ++ntp) {
            uint32_t b0, b1, b2, b3;
            ldsm_x4(b0, b1, b2, b3, bAddr + ks * 32 + ntp * (16 * PADW * 4));
            mma_f16(acc[2 * ntp][0], acc[2 * ntp][1], acc[2 * ntp][2], acc[2 * ntp][3],
                    a0, a1, a2, a3, b0, b1);
            mma_f16(acc[2 * ntp + 1][0], acc[2 * ntp + 1][1],
                    acc[2 * ntp + 1][2], acc[2 * ntp + 1][3],
                    a0, a1, a2, a3, b2, b3);
        }
    }
}

// ---------------------------------------------------------------------------
// Kernel 2: edge MLP + scatter.  128 edges/block, 8 warps = 4M x 2N groups.
// Pipeline tiles: 0..11 GEMM1 (A gather + W1 slice), 12..15 W2 slices.
// ---------------------------------------------------------------------------
__global__ __launch_bounds__(256, 2) void edge_kernel(
    const float* __restrict__ b1,
    const float* __restrict__ b2,
    const int*  __restrict__ src,
    const int*  __restrict__ dst)
{
    extern __shared__ char smem[];
    uint32_t* W = (uint32_t*)smem;
    int*   s_src = (int*)(smem + EDGE_MISC);
    int*   s_dst = (int*)(smem + EDGE_MISC + 512);
    float* s_b1  = (float*)(smem + EDGE_MISC + 1024);
    float* s_b2  = (float*)(smem + EDGE_MISC + 1536);
    const uint32_t sb = smem_u32(smem);

    const int tid  = threadIdx.x;
    const int wid  = tid >> 5;
    const int lane = tid & 31;
    const int e0   = blockIdx.x * 128;

    if (tid < 128) { s_src[tid] = src[e0 + tid];             s_b1[tid] = b1[tid]; }
    else           { s_dst[tid - 128] = dst[e0 + tid - 128]; s_b2[tid - 128] = b2[tid - 128]; }
    __syncthreads();

    const int lrow  = tid >> 1;
    const int lhalf = tid & 1;
    const int qr = lane >> 2;
    const int qc = lane & 3;
    const int wm = wid & 3;              // M group: rows [32*wm, 32*wm+32)
    const int wn = wid >> 2;             // N group: cols [64*wn, 64*wn+64)
    const int r0  = wm * 32;
    const int n0c = wn * 64;

    const uint32_t laneA = sb +
        (((uint32_t)(r0 + (lane & 7) + ((lane >> 3) & 1) * 8) * PADW + (lane >> 4) * 4) << 2);
    const uint32_t laneB = sb +
        (((uint32_t)(n0c + (lane & 7) + ((lane >> 4) & 1) * 8) * PADW + ((lane >> 3) & 1) * 4) << 2);

    const uint32_t stageOff = ((uint32_t)lrow * PADW + lhalf * 8) << 2;

    auto stage = [&](int t) {
        uint32_t bdst = sb + (3 + (t % 3)) * TILE_B + stageOff;
        if (t < 12) {
            const uint32_t* as;
            if (t < 4)      as = g_hh  + (size_t)s_src[lrow] * 64 + t * 16;
            else if (t < 8) as = g_hh  + (size_t)s_dst[lrow] * 64 + (t - 4) * 16;
            else            as = g_efh + (size_t)(e0 + lrow) * 64 + (t - 8) * 16;
            as += lhalf * 8;
            uint32_t adst = sb + (t % 3) * TILE_B + stageOff;
            cpa16(adst, as); cpa16(adst + 16, as + 4);
            const uint32_t* ws = g_w1t + lrow * 192 + t * 16 + lhalf * 8;
            cpa16(bdst, ws); cpa16(bdst + 16, ws + 4);
        } else {
            const uint32_t* ws = g_w2t + lrow * 64 + (t - 12) * 16 + lhalf * 8;
            cpa16(bdst, ws); cpa16(bdst + 16, ws + 4);
        }
        CPA_COMMIT();
    };

    float acc[16][4];
    #pragma unroll
    for (int g = 0; g < 16; ++g)
        #pragma unroll
        for (int j = 0; j < 4; ++j) acc[g][j] = 0.0f;

    stage(0);
    stage(1);

    // ---------------- GEMM1: 12 k-tiles ----------------
    for (int kt = 0; kt < 12; ++kt) {
        CPA_WAIT1();
        __syncthreads();
        stage(kt + 2);
        mma_tile32(acc, laneA + (kt % 3) * TILE_B, laneB + (3 + (kt % 3)) * TILE_B);
    }

    // ---- epilogue1: bias + silu -> f16 -> m1 tiles 6..9 --------------------
    #pragma unroll
    for (int g = 0; g < 16; ++g) {
        int mrow = g >> 3, n8 = g & 7;
        int c0 = n0c + n8 * 8 + 2 * qc;
        int tile = 6 + wn * 2 + (n8 >> 2);
        int word = tile * TILE_W + (n8 & 3) * 4 + qc;
        int rowA = r0 + mrow * 16 + qr;
        float v0 = silu(acc[g][0] + s_b1[c0]);
        float v1 = silu(acc[g][1] + s_b1[c0 + 1]);
        float v2 = silu(acc[g][2] + s_b1[c0]);
        float v3 = silu(acc[g][3] + s_b1[c0 + 1]);
        W[word + rowA * PADW]       = packh(v0, v1);
        W[word + (rowA + 8) * PADW] = packh(v2, v3);
        acc[g][0] = 0.f; acc[g][1] = 0.f; acc[g][2] = 0.f; acc[g][3] = 0.f;
    }

    // ---------------- GEMM2: 4 k-tiles (pipeline tiles 12..15) --------------
    for (int kt = 0; kt < 4; ++kt) {
        if (kt == 3) { CPA_WAIT0(); } else { CPA_WAIT1(); }
        __syncthreads();   // also publishes m1 writes across warps (kt==0)
        if (kt < 2) stage(14 + kt);
        mma_tile32(acc, laneA + (6 + kt) * TILE_B, laneB + (3 + ((12 + kt) % 3)) * TILE_B);
    }

    // ---- final epilogue: bias + silu + red.add.v2 scatter ------------------
    {
        const int rr[4] = { r0 + qr, r0 + qr + 8, r0 + 16 + qr, r0 + 24 + qr };
        float* base[4];
        #pragma unroll
        for (int i = 0; i < 4; ++i)
            base[i] = g_msum + (size_t)s_src[rr[i]] * D;
        #pragma unroll
        for (int g = 0; g < 16; ++g) {
            int mrow = g >> 3, n8 = g & 7;
            int c0 = n0c + n8 * 8 + 2 * qc;
            float v0 = silu(acc[g][0] + s_b2[c0]);
            float v1 = silu(acc[g][1] + s_b2[c0 + 1]);
            float v2 = silu(acc[g][2] + s_b2[c0]);
            float v3 = silu(acc[g][3] + s_b2[c0 + 1]);
            asm volatile("red.global.add.v2.f32 [%0], {%1,%2};"
                         :: "l"(base[mrow * 2] + c0), "f"(v0), "f"(v1) : "memory");
            asm volatile("red.global.add.v2.f32 [%0], {%1,%2};"
                         :: "l"(base[mrow * 2 + 1] + c0), "f"(v2), "f"(v3) : "memory");
        }
        if (wn == 0 && qc == 0) {
            #pragma unroll
            for (int i = 0; i < 4; ++i)
                atomicAdd(&g_cnt[s_src[rr[i]]], 1.0f);
        }
    }
}

// ---------------------------------------------------------------------------
// Kernel 3: node aggregation MLP + residual. 64 nodes/block, 4 warps.
// ---------------------------------------------------------------------------
__global__ __launch_bounds__(128, 3) void node_kernel(
    const float* __restrict__ nf,
    const float* __restrict__ b1,
    const float* __restrict__ b2,
    float* __restrict__ out)
{
    extern __shared__ char smem[];
    uint32_t* W = (uint32_t*)smem;
    float* s_inv = (float*)(smem + NODE_MISC);
    float* s_b1  = (float*)(smem + NODE_MISC + 512);
    float* s_b2  = (float*)(smem + NODE_MISC + 1024);
    const uint32_t sb = smem_u32(smem);

    const int tid  = threadIdx.x;
    const int wid  = tid >> 5;
    const int lane = tid & 31;
    const int n0   = blockIdx.x * 64;

    if (tid < 64) s_inv[tid] = 1.0f / fmaxf(g_cnt[n0 + tid], 1.0f);
    s_b1[tid] = b1[tid];
    s_b2[tid] = b2[tid];
    __syncthreads();

    const int lrow  = tid >> 1;
    const int lhalf = tid & 1;
    const int qr = lane >> 2;
    const int qc = lane & 3;
    const int r0 = wid * 16;

    const uint32_t laneA = sb +
        (((uint32_t)(r0 + (lane & 7) + ((lane >> 3) & 1) * 8) * PADW + (lane >> 4) * 4) << 2);
    const uint32_t laneB = sb +
        (((uint32_t)((lane & 7) + ((lane >> 4) & 1) * 8) * PADW + ((lane >> 3) & 1) * 4) << 2);

    float acc[16][4];
    #pragma unroll
    for (int nt = 0; nt < 16; ++nt)
        #pragma unroll
        for (int j = 0; j < 4; ++j) acc[nt][j] = 0.0f;

    // ---- GEMM1: concat(h, mean) [64 x 256] @ AW1t, 8 k-tiles ---------------
    for (int kt = 0; kt < 8; ++kt) {
        const int b = kt & 1;
        uint32_t* ap = W + b * TILE_W + lrow * PADW + lhalf * 8;

        if (kt < 4) {
            const uint32_t* as = g_hh + (size_t)(n0 + lrow) * 64 + kt * 16 + lhalf * 8;
            *(uint4*)(ap)     = *(const uint4*)(as);
            *(uint4*)(ap + 4) = *(const uint4*)(as + 4);
        } else {
            const float* ab = g_msum + (size_t)(n0 + lrow) * D + (kt & 3) * 32 + lhalf * 16;
            float inv = s_inv[lrow];
            uint32_t w[8];
            #pragma unroll
            for (int j = 0; j < 4; ++j) {
                float4 v = *(const float4*)(ab + j * 4);
                w[2 * j]     = packh(v.x * inv, v.y * inv);
                w[2 * j + 1] = packh(v.z * inv, v.w * inv);
            }
            *(uint4*)(ap)     = make_uint4(w[0], w[1], w[2], w[3]);
            *(uint4*)(ap + 4) = make_uint4(w[4], w[5], w[6], w[7]);
        }

        const uint32_t* wb = g_aw1t + tid * 128 + kt * 16;
        uint32_t* bp = W + (2 + b) * TILE_W + tid * PADW;
        #pragma unroll
        for (int j = 0; j < 4; ++j)
            *(uint4*)(bp + j * 4) = *(const uint4*)(wb + j * 4);
        __syncthreads();

        mma_tile(acc, laneA + b * TILE_B, laneB + (2 + b) * TILE_B);
        __syncthreads();
    }

    // ---- epilogue1 -> m1 tiles 0-3 ------------------------------------------
    #pragma unroll
    for (int nt = 0; nt < 16; ++nt) {
        int c0 = nt * 8 + 2 * qc;
        int wbase = (nt >> 2) * TILE_W + (nt & 3) * 4 + qc;
        float v0 = silu(acc[nt][0] + s_b1[c0]);
        float v1 = silu(acc[nt][1] + s_b1[c0 + 1]);
        float v2 = silu(acc[nt][2] + s_b1[c0]);
        float v3 = silu(acc[nt][3] + s_b1[c0 + 1]);
        W[wbase + (r0 + qr)     * PADW] = packh(v0, v1);
        W[wbase + (r0 + qr + 8) * PADW] = packh(v2, v3);
        acc[nt][0] = 0.f; acc[nt][1] = 0.f; acc[nt][2] = 0.f; acc[nt][3] = 0.f;
    }
    __syncthreads();

    // ---- GEMM2: [64 x 128] @ AW2t, 4 k-tiles --------------------------------
    for (int kt = 0; kt < 4; ++kt) {
        const int b = kt & 1;
        const uint32_t* wb = g_aw2t + tid * 64 + kt * 16;
        uint32_t* bp = W + (4 + b) * TILE_W + tid * PADW;
        #pragma unroll
        for (int j = 0; j < 4; ++j)
            *(uint4*)(bp + j * 4) = *(const uint4*)(wb + j * 4);
        __syncthreads();

        mma_tile(acc, laneA + kt * TILE_B, laneB + (4 + b) * TILE_B);
        __syncthreads();
    }

    // ---- final: bias + silu + residual -> out --------------------------------
    {
        const int nA = n0 + r0 + qr, nB = nA + 8;
        #pragma unroll
        for (int nt = 0; nt < 16; ++nt) {
            int c0 = nt * 8 + 2 * qc;
            float2 rA = *(const float2*)(nf + (size_t)nA * D + c0);
            float2 oA;
            oA.x = rA.x + silu(acc[nt][0] + s_b2[c0]);
            oA.y = rA.y + silu(acc[nt][1] + s_b2[c0 + 1]);
            *(float2*)(out + (size_t)nA * D + c0) = oA;
            float2 rB = *(const float2*)(nf + (size_t)nB * D + c0);
            float2 oB;
            oB.x = rB.x + silu(acc[nt][2] + s_b2[c0]);
            oB.y = rB.y + silu(acc[nt][3] + s_b2[c0 + 1]);
            *(float2*)(out + (size_t)nB * D + c0) = oB;
        }
    }
}

// ---------------------------------------------------------------------------
extern "C" void kernel_launch(void* const* d_in, const int* in_sizes, int n_in,
                              void* d_out, int out_size)
{
    const float* nf    = (const float*)d_in[0];
    const float* ef    = (const float*)d_in[1];
    const float* gamma = (const float*)d_in[2];
    const float* beta  = (const float*)d_in[3];
    const float* mw1   = (const float*)d_in[4];
    const float* mb1   = (const float*)d_in[5];
    const float* mw2   = (const float*)d_in[6];
    const float* mb2   = (const float*)d_in[7];
    const float* aw1   = (const float*)d_in[8];
    const float* ab1   = (const float*)d_in[9];
    const float* aw2   = (const float*)d_in[10];
    const float* ab2   = (const float*)d_in[11];
    const int*   eidx  = (const int*)d_in[12];
    float*       out   = (float*)d_out;

    const int* src = eidx;
    const int* dst = eidx + N_EDGES;

    cudaFuncSetAttribute(edge_kernel, cudaFuncAttributeMaxDynamicSharedMemorySize, EDGE_SMEM);
    cudaFuncSetAttribute(node_kernel, cudaFuncAttributeMaxDynamicSharedMemorySize, NODE_SMEM);

    prep_weights<<<224, 256>>>(mw1, mw2, aw1, aw2);
    ef2h_kernel<<<(N_EDGES * (D / 4)) / 256, 256>>>(ef);
    ln_kernel<<<N_NODES / 8, 256>>>(nf, gamma, beta);
    edge_kernel<<<N_EDGES / 128, 256, EDGE_SMEM>>>(mb1, mb2, src, dst);
    node_kernel<<<N_NODES / 64, 128, NODE_SMEM>>>(nf, ab1, ab2, out);
}